// round 12
// baseline (speedup 1.0000x reference)
#include <cuda_runtime.h>
#include <cuda_bf16.h>
#include <cstdint>

#define BATCH 16
#define C 256
#define D 64
#define NPIX 16384

// ---------------- device scratch (no runtime allocation) -------------------
__device__ __nv_bfloat16 g_ebf[(size_t)BATCH * D * NPIX];  // exp(logits), bf16, 32MB
__device__ float g_part[BATCH * D * 128];
__device__ float g_rowinv[BATCH * D];
__device__ __nv_bfloat16 g_W1p[4 * 2 * 64 * 72];           // [ck][plane][d][72] padded
__device__ float g_W2f[C * D];                             // fp32 bn-folded W2 [c][d]
__device__ __nv_bfloat16 g_W2b[BATCH * 2 * 256 * 72];      // per-batch W2*ri hi/lo planes
__device__ float g_b1[D];
__device__ float g_bias2[C];

// ---------------- helpers ---------------------------------------------------
__device__ __forceinline__ uint32_t smem_u32(const void* p) {
    uint32_t a;
    asm("{ .reg .u64 t; cvta.to.shared.u64 t, %1; cvt.u32.u64 %0, t; }" : "=r"(a) : "l"(p));
    return a;
}
__device__ __forceinline__ void ldm_x4(uint32_t addr, uint32_t* r) {
    asm volatile("ldmatrix.sync.aligned.m8n8.x4.shared.b16 {%0,%1,%2,%3}, [%4];"
        : "=r"(r[0]), "=r"(r[1]), "=r"(r[2]), "=r"(r[3]) : "r"(addr));
}
__device__ __forceinline__ void ldm_x4t(uint32_t addr, uint32_t* r) {
    asm volatile("ldmatrix.sync.aligned.m8n8.x4.trans.shared.b16 {%0,%1,%2,%3}, [%4];"
        : "=r"(r[0]), "=r"(r[1]), "=r"(r[2]), "=r"(r[3]) : "r"(addr));
}
__device__ __forceinline__ void mma_bf16(float* d, const uint32_t* a, uint32_t b0, uint32_t b1) {
    asm volatile(
        "mma.sync.aligned.m16n8k16.row.col.f32.bf16.bf16.f32 "
        "{%0,%1,%2,%3}, {%4,%5,%6,%7}, {%8,%9}, {%0,%1,%2,%3};"
        : "+f"(d[0]), "+f"(d[1]), "+f"(d[2]), "+f"(d[3])
        : "r"(a[0]), "r"(a[1]), "r"(a[2]), "r"(a[3]), "r"(b0), "r"(b1));
}
__device__ __forceinline__ void cp16(uint32_t dst, const void* src) {
    asm volatile("cp.async.ca.shared.global [%0], [%1], 16;" :: "r"(dst), "l"(src));
}
__device__ __forceinline__ void cp_commit() { asm volatile("cp.async.commit_group;"); }
__device__ __forceinline__ void cp_wait0() { asm volatile("cp.async.wait_group 0;" ::: "memory"); }

// exp via FMA-pipe polynomial (no MUFU); rel err ~2e-6
__device__ __forceinline__ float fexp(float v) {
    float t = v * 1.44269504f;
    t = fminf(fmaxf(t, -120.f), 120.f);
    float r = rintf(t);
    float f = t - r;
    float q = 0.0013333558f;
    q = fmaf(q, f, 0.0096181291f);
    q = fmaf(q, f, 0.0555041087f);
    q = fmaf(q, f, 0.2402265069f);
    q = fmaf(q, f, 0.6931471806f);
    q = fmaf(q, f, 1.0f);
    return __int_as_float(((int)r + 127) << 23) * q;
}
__device__ __forceinline__ void split_bf16(float v, __nv_bfloat16& hi, __nv_bfloat16& lo) {
    hi = __float2bfloat16(v);
    lo = __float2bfloat16(v - __bfloat162float(hi));
}

// ---------------------------------------------------------------------------
// K0: fold weights + BN.  W1 -> padded hi/lo planes; W2 -> fp32 [c][d].
// ---------------------------------------------------------------------------
__global__ __launch_bounds__(256) void prep_kernel(
    const float* __restrict__ conv1_w, const float* __restrict__ conv1_b,
    const float* __restrict__ mk_w,    const float* __restrict__ mv_w,
    const float* __restrict__ conv2_w, const float* __restrict__ bn_gamma,
    const float* __restrict__ bn_beta, const float* __restrict__ bn_mean,
    const float* __restrict__ bn_var)
{
    int gid = blockIdx.x * blockDim.x + threadIdx.x;
    if (gid < D * C) {
        int d = gid >> 8, c = gid & 255;
        float s = 0.f;
        for (int o = 0; o < C; o++)
            s = fmaf(mk_w[d * C + o], conv1_w[o * C + c], s);
        __nv_bfloat16 hi, lo; split_bf16(s, hi, lo);
        int ck = c >> 6, cl = c & 63;
        g_W1p[ck * 9216 + d * 72 + cl] = hi;
        g_W1p[ck * 9216 + 4608 + d * 72 + cl] = lo;
    } else if (gid < 2 * D * C) {
        int j = gid - D * C;
        int c = j >> 6, d = j & 63;
        float inv = bn_gamma[c] * rsqrtf(bn_var[c] + 1e-5f);
        float s = 0.f;
        for (int cp = 0; cp < C; cp++)
            s = fmaf(conv2_w[c * C + cp], mv_w[cp * D + d], s);
        g_W2f[c * D + d] = s * inv;
    } else if (gid < 2 * D * C + D) {
        int d = gid - 2 * D * C;
        float s = 0.f;
        for (int o = 0; o < C; o++)
            s = fmaf(mk_w[d * C + o], conv1_b[o], s);
        g_b1[d] = s;
    } else if (gid < 2 * D * C + D + C) {
        int c = gid - 2 * D * C - D;
        float inv = bn_gamma[c] * rsqrtf(bn_var[c] + 1e-5f);
        g_bias2[c] = bn_beta[c] - bn_mean[c] * inv;
    }
}

// ---------------------------------------------------------------------------
// K1: e = exp(W1 @ x + b1) -> bf16, + per-block row partial sums.
// Double-buffered pipeline: W via cp.async, x via register-wave prefetch.
// smem ~71KB -> 3 CTAs/SM.
// ---------------------------------------------------------------------------
#define K1_X0 0
#define K1_X1 17408
#define K1_W0 34816
#define K1_W1 53248
#define K1_B1 71680
#define K1_SPART 71936
#define K1_SMEM 72960

__global__ __launch_bounds__(256, 3) void logits_kernel(const float* __restrict__ x)
{
    extern __shared__ char sh[];
    uint32_t sb = smem_u32(sh);
    float* b1s   = (float*)(sh + K1_B1);
    float* spart = (float*)(sh + K1_SPART);
    int tid = threadIdx.x, w = tid >> 5, lane = tid & 31;
    int b = blockIdx.y, mblk = blockIdx.x, pix0 = mblk * 128;

    if (tid < 64) b1s[tid] = g_b1[tid];

    int wm = w & 3, wq = w >> 2;
    int m0 = wm * 32, n0 = wq * 32;
    uint32_t a_k = (lane & 7) + ((lane >> 4) << 3);
    uint32_t a_mo = ((lane >> 3) & 1) * 8;
    uint32_t b_row = lane & 15;
    uint32_t b_co = (lane >> 4) << 4;
    int p2 = (tid & 63) * 2;
    int cg = tid >> 6;

    float acc[2][4][4];
#pragma unroll
    for (int t = 0; t < 2; t++)
#pragma unroll
        for (int q = 0; q < 4; q++)
#pragma unroll
            for (int i = 0; i < 4; i++) acc[t][q][i] = 0.f;

    // prologue: W0 via cp.async, X0 staged directly
#pragma unroll
    for (int k = 0; k < 5; k++) {
        int idx = tid + k * 256;
        if (idx < 1152) cp16(sb + K1_W0 + idx * 16, (const char*)g_W1p + idx * 16);
    }
    cp_commit();
    {
        const float* xp = x + ((size_t)b * C + cg * 16) * NPIX + pix0 + p2;
        char* xh = sh + K1_X0 + (size_t)cg * 16 * 272 + p2 * 2;
#pragma unroll
        for (int jb = 0; jb < 2; jb++) {
            float2 v[8];
#pragma unroll
            for (int u = 0; u < 8; u++)
                v[u] = *(const float2*)(xp + (size_t)(jb * 8 + u) * NPIX);
#pragma unroll
            for (int u = 0; u < 8; u++) {
                __nv_bfloat162 hp;
                hp.x = __float2bfloat16(v[u].x);
                hp.y = __float2bfloat16(v[u].y);
                *(__nv_bfloat162*)(xh + (jb * 8 + u) * 272) = hp;
            }
        }
    }
    cp_wait0();
    __syncthreads();

    for (int ck = 0; ck < 4; ck++) {
        int cur = ck & 1;
        uint32_t xb = cur ? K1_X1 : K1_X0;
        uint32_t wb = cur ? K1_W1 : K1_W0;
        uint32_t xnb = cur ? K1_X0 : K1_X1;
        uint32_t wnb = cur ? K1_W0 : K1_W1;

        const float* xpn = x + ((size_t)b * C + (ck + 1) * 64 + cg * 16) * NPIX + pix0 + p2;
        float2 v[8];
        if (ck < 3) {
            // async W prefetch + first x wave LDG (lands under MMA)
#pragma unroll
            for (int k = 0; k < 5; k++) {
                int idx = tid + k * 256;
                if (idx < 1152)
                    cp16(sb + wnb + idx * 16,
                         (const char*)g_W1p + (ck + 1) * 18432 + idx * 16);
            }
            cp_commit();
#pragma unroll
            for (int u = 0; u < 8; u++)
                v[u] = *(const float2*)(xpn + (size_t)u * NPIX);
        }

        // MMA on current buffers
#pragma unroll
        for (int kk = 0; kk < 4; kk++) {
            uint32_t ah[2][4];
#pragma unroll
            for (int t = 0; t < 2; t++) {
                uint32_t off = (kk * 16 + a_k) * 272 + (m0 + t * 16 + a_mo) * 2;
                ldm_x4t(sb + xb + off, ah[t]);
            }
            uint32_t bh[2][4], bl[2][4];
#pragma unroll
            for (int q = 0; q < 2; q++) {
                uint32_t off = (n0 + q * 16 + b_row) * 144 + kk * 32 + b_co;
                ldm_x4(sb + wb + off, bh[q]);
                ldm_x4(sb + wb + 9216 + off, bl[q]);
            }
#pragma unroll
            for (int t = 0; t < 2; t++)
#pragma unroll
                for (int q = 0; q < 2; q++) {
                    mma_bf16(acc[t][q * 2], ah[t], bh[q][0], bh[q][2]);
                    mma_bf16(acc[t][q * 2], ah[t], bl[q][0], bl[q][2]);
                    mma_bf16(acc[t][q * 2 + 1], ah[t], bh[q][1], bh[q][3]);
                    mma_bf16(acc[t][q * 2 + 1], ah[t], bl[q][1], bl[q][3]);
                }
        }

        if (ck < 3) {
            char* xh = sh + xnb + (size_t)cg * 16 * 272 + p2 * 2;
            // store wave A
#pragma unroll
            for (int u = 0; u < 8; u++) {
                __nv_bfloat162 hp;
                hp.x = __float2bfloat16(v[u].x);
                hp.y = __float2bfloat16(v[u].y);
                *(__nv_bfloat162*)(xh + u * 272) = hp;
            }
            // wave B: load + store
#pragma unroll
            for (int u = 0; u < 8; u++)
                v[u] = *(const float2*)(xpn + (size_t)(8 + u) * NPIX);
#pragma unroll
            for (int u = 0; u < 8; u++) {
                __nv_bfloat162 hp;
                hp.x = __float2bfloat16(v[u].x);
                hp.y = __float2bfloat16(v[u].y);
                *(__nv_bfloat162*)(xh + (8 + u) * 272) = hp;
            }
            cp_wait0();
        }
        __syncthreads();
    }

    // epilogue: exp -> bf16 z-tile [d][128 pix] in smem, + row partials
    __nv_bfloat16* ztb = (__nv_bfloat16*)(sh + K1_X0);
    int dbase = n0 + (lane & 3) * 2;
    int plocal = m0 + (lane >> 2);
#pragma unroll
    for (int q = 0; q < 4; q++) {
        int d0 = dbase + q * 8;
        float bb0 = b1s[d0], bb1 = b1s[d0 + 1];
        float s0 = 0.f, s1 = 0.f;
#pragma unroll
        for (int t = 0; t < 2; t++) {
            int p0 = plocal + t * 16, p1 = p0 + 8;
            float v00 = fexp(acc[t][q][0] + bb0); ztb[d0 * 128 + p0] = __float2bfloat16(v00);
            float v01 = fexp(acc[t][q][1] + bb1); ztb[(d0 + 1) * 128 + p0] = __float2bfloat16(v01);
            float v02 = fexp(acc[t][q][2] + bb0); ztb[d0 * 128 + p1] = __float2bfloat16(v02);
            float v03 = fexp(acc[t][q][3] + bb1); ztb[(d0 + 1) * 128 + p1] = __float2bfloat16(v03);
            s0 += v00 + v02; s1 += v01 + v03;
        }
        s0 += __shfl_xor_sync(0xFFFFFFFF, s0, 4);
        s0 += __shfl_xor_sync(0xFFFFFFFF, s0, 8);
        s0 += __shfl_xor_sync(0xFFFFFFFF, s0, 16);
        s1 += __shfl_xor_sync(0xFFFFFFFF, s1, 4);
        s1 += __shfl_xor_sync(0xFFFFFFFF, s1, 8);
        s1 += __shfl_xor_sync(0xFFFFFFFF, s1, 16);
        if (lane < 4) {
            spart[d0 * 4 + wm] = s0;
            spart[(d0 + 1) * 4 + wm] = s1;
        }
    }
    __syncthreads();
    if (tid < 64) {
        float s = spart[tid * 4] + spart[tid * 4 + 1] + spart[tid * 4 + 2] + spart[tid * 4 + 3];
        g_part[(b * D + tid) * 128 + mblk] = s;
    }
    // coalesced bf16 store: 1024 x 16B items
#pragma unroll
    for (int k = 0; k < 4; k++) {
        int idx = tid + k * 256;
        int row = idx >> 4, ch = idx & 15;
        uint4 vv = *(uint4*)((char*)ztb + row * 256 + ch * 16);
        *(uint4*)((char*)g_ebf + ((size_t)(b * D + row) * NPIX + pix0) * 2 + ch * 16) = vv;
    }
}

// ---------------------------------------------------------------------------
// K2: rowinv + per-batch W2' = W2 * ri[d] -> padded bf16 hi/lo planes.
// ---------------------------------------------------------------------------
__global__ __launch_bounds__(256) void rowinv_kernel()
{
    __shared__ float ri_s[64];
    __shared__ float red[256];
    int b = blockIdx.x, tid = threadIdx.x;
    int r = tid >> 2, qq = tid & 3;
    float s = 0.f;
#pragma unroll
    for (int i = 0; i < 32; i++)
        s += g_part[(b * D + r) * 128 + qq * 32 + i];
    red[tid] = s;
    __syncthreads();
    if (qq == 0) {
        float t = red[tid] + red[tid + 1] + red[tid + 2] + red[tid + 3];
        float ri = 1.f / t;
        ri_s[r] = ri;
        g_rowinv[b * D + r] = ri;
    }
    __syncthreads();
#pragma unroll
    for (int k = 0; k < 64; k++) {
        int idx = tid + k * 256;
        int c = idx >> 6, d = idx & 63;
        float wv = g_W2f[idx] * ri_s[d];
        __nv_bfloat16 hi, lo; split_bf16(wv, hi, lo);
        g_W2b[(size_t)b * 36864 + c * 72 + d] = hi;
        g_W2b[(size_t)b * 36864 + 18432 + c * 72 + d] = lo;
    }
}

// ---------------------------------------------------------------------------
// K3: out = relu(W2' @ e * scale + bias2 + x); scale = 1/(1e-9 + colsum(ri*e)).
// (unchanged from R11: 128 pix x 64 c, bf16 A, 4 CTAs/SM)
// ---------------------------------------------------------------------------
#define K3_A  0
#define K3_W  17408
#define K3_RI (K3_W + 18432)
#define K3_B2 (K3_RI + 256)
#define K3_CS (K3_B2 + 256)
#define K3_SC (K3_CS + 2048)
#define K3_SMEM (K3_SC + 512)

__global__ __launch_bounds__(256, 4) void output_kernel(const float* __restrict__ x,
                                                        float* __restrict__ out)
{
    extern __shared__ char sh[];
    uint32_t sb = smem_u32(sh);
    float* ri_s = (float*)(sh + K3_RI);
    float* b2_s = (float*)(sh + K3_B2);
    float* cs   = (float*)(sh + K3_CS);
    float* sc_s = (float*)(sh + K3_SC);
    int tid = threadIdx.x, w = tid >> 5, lane = tid & 31;
    int b = blockIdx.y;
    int cblk = blockIdx.x & 3, pixblk = blockIdx.x >> 2;
    int pix0 = pixblk * 128, cb0 = cblk * 64;

#pragma unroll
    for (int k = 0; k < 4; k++) {
        int idx = tid + k * 256;
        int d = idx >> 4, ch = idx & 15;
        cp16(sb + K3_A + d * 272 + ch * 16,
             (const char*)g_ebf + ((size_t)(b * D + d) * NPIX + pix0) * 2 + ch * 16);
    }
#pragma unroll
    for (int k = 0; k < 5; k++) {
        int idx = tid + k * 256;
        if (idx < 1152) {
            int plane = idx / 576, r = idx % 576;
            cp16(sb + K3_W + plane * 9216 + r * 16,
                 (const char*)g_W2b + (size_t)b * 73728 + plane * 36864 + cb0 * 144 + r * 16);
        }
    }
    cp_commit();
    if (tid < 64) {
        ri_s[tid] = g_rowinv[b * D + tid];
        b2_s[tid] = g_bias2[cb0 + tid];
    }
    cp_wait0();
    __syncthreads();

    // colsum over d of ri*e -> per-pixel scale (bf16x2 vectorized)
    {
        int pair = tid & 63;
        int dg = tid >> 6;
        float s0 = 0.f, s1 = 0.f;
#pragma unroll
        for (int j = 0; j < 16; j++) {
            int d = dg * 16 + j;
            __nv_bfloat162 e2 = *(const __nv_bfloat162*)(sh + K3_A + d * 272 + pair * 4);
            float ri = ri_s[d];
            s0 = fmaf(__bfloat162float(e2.x), ri, s0);
            s1 = fmaf(__bfloat162float(e2.y), ri, s1);
        }
        cs[dg * 128 + pair * 2]     = s0;
        cs[dg * 128 + pair * 2 + 1] = s1;
    }
    __syncthreads();
    if (tid < 128)
        sc_s[tid] = 1.f / (1e-9f + cs[tid] + cs[128 + tid] + cs[256 + tid] + cs[384 + tid]);
    __syncthreads();

    int wm = w & 3, wq = w >> 2;
    int m0 = wm * 32, n0 = wq * 32;
    uint32_t a_k = (lane & 7) + ((lane >> 4) << 3);
    uint32_t a_mo = ((lane >> 3) & 1) * 8;
    uint32_t b_row = lane & 15;
    uint32_t b_co = (lane >> 4) << 4;

    float acc[2][4][4];
#pragma unroll
    for (int t = 0; t < 2; t++)
#pragma unroll
        for (int q = 0; q < 4; q++)
#pragma unroll
            for (int i = 0; i < 4; i++) acc[t][q][i] = 0.f;

#pragma unroll
    for (int kk = 0; kk < 4; kk++) {
        uint32_t ah[2][4];
#pragma unroll
        for (int t = 0; t < 2; t++) {
            uint32_t off = (kk * 16 + a_k) * 272 + (m0 + t * 16 + a_mo) * 2;
            ldm_x4t(sb + K3_A + off, ah[t]);
        }
#pragma unroll
        for (int q = 0; q < 2; q++) {
            uint32_t off = (n0 + q * 16 + b_row) * 144 + kk * 32 + b_co;
            uint32_t bh[4], bl[4];
            ldm_x4(sb + K3_W + off, bh);
            ldm_x4(sb + K3_W + 9216 + off, bl);
#pragma unroll
            for (int t = 0; t < 2; t++) {
                mma_bf16(acc[t][q * 2], ah[t], bh[0], bh[2]);
                mma_bf16(acc[t][q * 2], ah[t], bl[0], bl[2]);
                mma_bf16(acc[t][q * 2 + 1], ah[t], bh[1], bh[3]);
                mma_bf16(acc[t][q * 2 + 1], ah[t], bl[1], bl[3]);
            }
        }
    }

    __syncthreads();
    float* zt = (float*)sh;
    {
        int clb = n0 + (lane & 3) * 2;
        int plocal = m0 + (lane >> 2);
#pragma unroll
        for (int t = 0; t < 2; t++) {
            int p0 = plocal + t * 16, p1 = p0 + 8;
#pragma unroll
            for (int q = 0; q < 4; q++) {
                int cl = clb + q * 8;
                zt[cl * 128 + p0]       = acc[t][q][0];
                zt[(cl + 1) * 128 + p0] = acc[t][q][1];
                zt[cl * 128 + p1]       = acc[t][q][2];
                zt[(cl + 1) * 128 + p1] = acc[t][q][3];
            }
        }
    }
    __syncthreads();

#pragma unroll
    for (int k = 0; k < 8; k++) {
        int idx = tid + k * 256;
        int row = idx >> 5, col = idx & 31;
        float4 z4 = ((const float4*)zt)[row * 32 + col];
        float4 sc4 = *(const float4*)(sc_s + col * 4);
        float bb = b2_s[row];
        size_t go = ((size_t)(b * C + cb0 + row)) * NPIX + pix0 + col * 4;
        float4 x4 = *(const float4*)(x + go);
        float4 o;
        o.x = fmaxf(fmaf(z4.x, sc4.x, bb) + x4.x, 0.f);
        o.y = fmaxf(fmaf(z4.y, sc4.y, bb) + x4.y, 0.f);
        o.z = fmaxf(fmaf(z4.z, sc4.z, bb) + x4.z, 0.f);
        o.w = fmaxf(fmaf(z4.w, sc4.w, bb) + x4.w, 0.f);
        *(float4*)(out + go) = o;
    }
}

// ---------------------------------------------------------------------------
extern "C" void kernel_launch(void* const* d_in, const int* in_sizes, int n_in,
                              void* d_out, int out_size)
{
    const float* x       = (const float*)d_in[0];
    const float* conv1_w = (const float*)d_in[1];
    const float* conv1_b = (const float*)d_in[2];
    const float* mk_w    = (const float*)d_in[3];
    const float* mv_w    = (const float*)d_in[4];
    const float* conv2_w = (const float*)d_in[5];
    const float* gamma   = (const float*)d_in[6];
    const float* beta    = (const float*)d_in[7];
    const float* mean    = (const float*)d_in[8];
    const float* var     = (const float*)d_in[9];
    float* out = (float*)d_out;

    cudaFuncSetAttribute(logits_kernel, cudaFuncAttributeMaxDynamicSharedMemorySize, K1_SMEM);
    cudaFuncSetAttribute(output_kernel, cudaFuncAttributeMaxDynamicSharedMemorySize, K3_SMEM);

    prep_kernel<<<130, 256>>>(conv1_w, conv1_b, mk_w, mv_w, conv2_w,
                              gamma, beta, mean, var);

    dim3 g1(NPIX / 128, BATCH);
    logits_kernel<<<g1, 256, K1_SMEM>>>(x);

    rowinv_kernel<<<BATCH, 256>>>();

    dim3 g3((NPIX / 128) * 4, BATCH);
    output_kernel<<<g3, 256, K3_SMEM>>>(x, out);
}

// round 13
// speedup vs baseline: 1.0123x; 1.0123x over previous
#include <cuda_runtime.h>
#include <cuda_bf16.h>
#include <cstdint>

#define BATCH 16
#define C 256
#define D 64
#define NPIX 16384

// ---------------- device scratch (no runtime allocation) -------------------
__device__ __nv_bfloat16 g_ebf[(size_t)BATCH * D * NPIX];  // exp(logits), bf16, 32MB
__device__ float g_part[BATCH * D * 256];
__device__ float g_rowinv[BATCH * D];
__device__ __nv_bfloat16 g_W1p[4 * 2 * 64 * 72];           // [ck][plane][d][72] padded
__device__ float g_W2f[C * D];                             // fp32 bn-folded W2 [c][d]
__device__ __nv_bfloat16 g_W2b[BATCH * 2 * 256 * 72];      // per-batch W2*ri hi/lo planes
__device__ float g_b1[D];
__device__ float g_bias2[C];

// ---------------- helpers ---------------------------------------------------
__device__ __forceinline__ uint32_t smem_u32(const void* p) {
    uint32_t a;
    asm("{ .reg .u64 t; cvta.to.shared.u64 t, %1; cvt.u32.u64 %0, t; }" : "=r"(a) : "l"(p));
    return a;
}
__device__ __forceinline__ void ldm_x4(uint32_t addr, uint32_t* r) {
    asm volatile("ldmatrix.sync.aligned.m8n8.x4.shared.b16 {%0,%1,%2,%3}, [%4];"
        : "=r"(r[0]), "=r"(r[1]), "=r"(r[2]), "=r"(r[3]) : "r"(addr));
}
__device__ __forceinline__ void ldm_x4t(uint32_t addr, uint32_t* r) {
    asm volatile("ldmatrix.sync.aligned.m8n8.x4.trans.shared.b16 {%0,%1,%2,%3}, [%4];"
        : "=r"(r[0]), "=r"(r[1]), "=r"(r[2]), "=r"(r[3]) : "r"(addr));
}
__device__ __forceinline__ void mma_bf16(float* d, const uint32_t* a, uint32_t b0, uint32_t b1) {
    asm volatile(
        "mma.sync.aligned.m16n8k16.row.col.f32.bf16.bf16.f32 "
        "{%0,%1,%2,%3}, {%4,%5,%6,%7}, {%8,%9}, {%0,%1,%2,%3};"
        : "+f"(d[0]), "+f"(d[1]), "+f"(d[2]), "+f"(d[3])
        : "r"(a[0]), "r"(a[1]), "r"(a[2]), "r"(a[3]), "r"(b0), "r"(b1));
}
__device__ __forceinline__ void cp16(uint32_t dst, const void* src) {
    asm volatile("cp.async.ca.shared.global [%0], [%1], 16;" :: "r"(dst), "l"(src));
}
__device__ __forceinline__ void cp_commit() { asm volatile("cp.async.commit_group;"); }
__device__ __forceinline__ void cp_wait0() { asm volatile("cp.async.wait_group 0;" ::: "memory"); }

// exp via FMA-pipe polynomial (no MUFU); rel err ~2e-6
__device__ __forceinline__ float fexp(float v) {
    float t = v * 1.44269504f;
    t = fminf(fmaxf(t, -120.f), 120.f);
    float r = rintf(t);
    float f = t - r;
    float q = 0.0013333558f;
    q = fmaf(q, f, 0.0096181291f);
    q = fmaf(q, f, 0.0555041087f);
    q = fmaf(q, f, 0.2402265069f);
    q = fmaf(q, f, 0.6931471806f);
    q = fmaf(q, f, 1.0f);
    return __int_as_float(((int)r + 127) << 23) * q;
}
__device__ __forceinline__ void split_bf16(float v, __nv_bfloat16& hi, __nv_bfloat16& lo) {
    hi = __float2bfloat16(v);
    lo = __float2bfloat16(v - __bfloat162float(hi));
}

// ---------------------------------------------------------------------------
// K0: fold weights + BN.  W1 -> padded hi/lo planes; W2 -> fp32 [c][d].
// ---------------------------------------------------------------------------
__global__ __launch_bounds__(256) void prep_kernel(
    const float* __restrict__ conv1_w, const float* __restrict__ conv1_b,
    const float* __restrict__ mk_w,    const float* __restrict__ mv_w,
    const float* __restrict__ conv2_w, const float* __restrict__ bn_gamma,
    const float* __restrict__ bn_beta, const float* __restrict__ bn_mean,
    const float* __restrict__ bn_var)
{
    int gid = blockIdx.x * blockDim.x + threadIdx.x;
    if (gid < D * C) {
        int d = gid >> 8, c = gid & 255;
        float s = 0.f;
        for (int o = 0; o < C; o++)
            s = fmaf(mk_w[d * C + o], conv1_w[o * C + c], s);
        __nv_bfloat16 hi, lo; split_bf16(s, hi, lo);
        int ck = c >> 6, cl = c & 63;
        g_W1p[ck * 9216 + d * 72 + cl] = hi;
        g_W1p[ck * 9216 + 4608 + d * 72 + cl] = lo;
    } else if (gid < 2 * D * C) {
        int j = gid - D * C;
        int c = j >> 6, d = j & 63;
        float inv = bn_gamma[c] * rsqrtf(bn_var[c] + 1e-5f);
        float s = 0.f;
        for (int cp = 0; cp < C; cp++)
            s = fmaf(conv2_w[c * C + cp], mv_w[cp * D + d], s);
        g_W2f[c * D + d] = s * inv;
    } else if (gid < 2 * D * C + D) {
        int d = gid - 2 * D * C;
        float s = 0.f;
        for (int o = 0; o < C; o++)
            s = fmaf(mk_w[d * C + o], conv1_b[o], s);
        g_b1[d] = s;
    } else if (gid < 2 * D * C + D + C) {
        int c = gid - 2 * D * C - D;
        float inv = bn_gamma[c] * rsqrtf(bn_var[c] + 1e-5f);
        g_bias2[c] = bn_beta[c] - bn_mean[c] * inv;
    }
}

// ---------------------------------------------------------------------------
// K1: e = exp(W1 @ x + b1) -> bf16, + per-block row partial sums.
// Tile 64 pix (M) x 64 d (N), K=256 in 4 chunks of 64.
// Double-buffered X and W, ~56KB smem -> 4 CTAs/SM, reg-light prefetch.
// ---------------------------------------------------------------------------
#define K1_X0 0
#define K1_X1 9216
#define K1_W0 18432
#define K1_W1 36864
#define K1_B1 55296
#define K1_SPART 55552
#define K1_SMEM 56064

__global__ __launch_bounds__(256, 4) void logits_kernel(const float* __restrict__ x)
{
    extern __shared__ char sh[];
    uint32_t sb = smem_u32(sh);
    float* b1s   = (float*)(sh + K1_B1);
    float* spart = (float*)(sh + K1_SPART);
    int tid = threadIdx.x, w = tid >> 5, lane = tid & 31;
    int b = blockIdx.y, mblk = blockIdx.x, pix0 = mblk * 64;

    if (tid < 64) b1s[tid] = g_b1[tid];

    int wm = w & 1, wq = w >> 1;            // 2 m-warps x 4 n-warps
    int m0 = wm * 32, n0 = wq * 16;
    uint32_t a_k = (lane & 7) + ((lane >> 4) << 3);
    uint32_t a_mo = ((lane >> 3) & 1) * 8;
    uint32_t b_row = lane & 15;
    uint32_t b_co = (lane >> 4) << 4;
    int p2 = (tid & 31) * 2;                // pixel pair
    int rg = tid >> 5;                      // row group: 8 c rows per thread

    float acc[2][2][4];
#pragma unroll
    for (int t = 0; t < 2; t++)
#pragma unroll
        for (int n = 0; n < 2; n++)
#pragma unroll
            for (int i = 0; i < 4; i++) acc[t][n][i] = 0.f;

    // prologue: W0 cp.async + X0 direct
#pragma unroll
    for (int k = 0; k < 5; k++) {
        int idx = tid + k * 256;
        if (idx < 1152) cp16(sb + K1_W0 + idx * 16, (const char*)g_W1p + idx * 16);
    }
    cp_commit();
    {
        const float* xp = x + ((size_t)b * C + rg * 8) * NPIX + pix0 + p2;
        char* xh = sh + K1_X0 + (size_t)(rg * 8) * 144 + p2 * 2;
#pragma unroll
        for (int j = 0; j < 8; j++) {
            float2 v = *(const float2*)(xp + (size_t)j * NPIX);
            *(__nv_bfloat162*)(xh + j * 144) = __float22bfloat162_rn(v);
        }
    }
    cp_wait0();
    __syncthreads();

    for (int ck = 0; ck < 4; ck++) {
        int cur = ck & 1;
        uint32_t xb = cur ? K1_X1 : K1_X0;
        uint32_t wb = cur ? K1_W1 : K1_W0;
        uint32_t xnb = cur ? K1_X0 : K1_X1;
        uint32_t wnb = cur ? K1_W0 : K1_W1;

        const float* xpn = x + ((size_t)b * C + (ck + 1) * 64 + rg * 8) * NPIX + pix0 + p2;
        float2 vA[4];
        if (ck < 3) {
#pragma unroll
            for (int k = 0; k < 5; k++) {
                int idx = tid + k * 256;
                if (idx < 1152)
                    cp16(sb + wnb + idx * 16,
                         (const char*)g_W1p + (ck + 1) * 18432 + idx * 16);
            }
            cp_commit();
#pragma unroll
            for (int u = 0; u < 4; u++)
                vA[u] = *(const float2*)(xpn + (size_t)u * NPIX);
        }

        // MMA on current buffers
#pragma unroll
        for (int kk = 0; kk < 4; kk++) {
            uint32_t ah[2][4];
#pragma unroll
            for (int t = 0; t < 2; t++) {
                uint32_t off = (kk * 16 + a_k) * 144 + (m0 + t * 16 + a_mo) * 2;
                ldm_x4t(sb + xb + off, ah[t]);
            }
            uint32_t bh[4], bl[4];
            {
                uint32_t off = (n0 + b_row) * 144 + kk * 32 + b_co;
                ldm_x4(sb + wb + off, bh);
                ldm_x4(sb + wb + 9216 + off, bl);
            }
#pragma unroll
            for (int t = 0; t < 2; t++) {
                mma_bf16(acc[t][0], ah[t], bh[0], bh[2]);
                mma_bf16(acc[t][0], ah[t], bl[0], bl[2]);
                mma_bf16(acc[t][1], ah[t], bh[1], bh[3]);
                mma_bf16(acc[t][1], ah[t], bl[1], bl[3]);
            }
        }

        if (ck < 3) {
            char* xh = sh + xnb + (size_t)(rg * 8) * 144 + p2 * 2;
#pragma unroll
            for (int u = 0; u < 4; u++)
                *(__nv_bfloat162*)(xh + u * 144) = __float22bfloat162_rn(vA[u]);
#pragma unroll
            for (int u = 0; u < 4; u++) {
                float2 v = *(const float2*)(xpn + (size_t)(4 + u) * NPIX);
                *(__nv_bfloat162*)(xh + (4 + u) * 144) = __float22bfloat162_rn(v);
            }
            cp_wait0();
        }
        __syncthreads();
    }

    // epilogue: exp -> bf16 z-tile [d][64 pix] (144B rows, reuses X region)
    __nv_bfloat16* dummy = 0; (void)dummy;
    char* ztb = sh + K1_X0;
    int dbase = n0 + (lane & 3) * 2;
    int plocal = m0 + (lane >> 2);
#pragma unroll
    for (int n = 0; n < 2; n++) {
        int d0 = dbase + n * 8;
        float bb0 = b1s[d0], bb1 = b1s[d0 + 1];
        float s0 = 0.f, s1 = 0.f;
#pragma unroll
        for (int t = 0; t < 2; t++) {
            int p0 = plocal + t * 16, p1 = p0 + 8;
            float v00 = fexp(acc[t][n][0] + bb0);
            float v01 = fexp(acc[t][n][1] + bb1);
            float v02 = fexp(acc[t][n][2] + bb0);
            float v03 = fexp(acc[t][n][3] + bb1);
            *(__nv_bfloat16*)(ztb + d0 * 144 + p0 * 2) = __float2bfloat16(v00);
            *(__nv_bfloat16*)(ztb + (d0 + 1) * 144 + p0 * 2) = __float2bfloat16(v01);
            *(__nv_bfloat16*)(ztb + d0 * 144 + p1 * 2) = __float2bfloat16(v02);
            *(__nv_bfloat16*)(ztb + (d0 + 1) * 144 + p1 * 2) = __float2bfloat16(v03);
            s0 += v00 + v02; s1 += v01 + v03;
        }
        s0 += __shfl_xor_sync(0xFFFFFFFF, s0, 4);
        s0 += __shfl_xor_sync(0xFFFFFFFF, s0, 8);
        s0 += __shfl_xor_sync(0xFFFFFFFF, s0, 16);
        s1 += __shfl_xor_sync(0xFFFFFFFF, s1, 4);
        s1 += __shfl_xor_sync(0xFFFFFFFF, s1, 8);
        s1 += __shfl_xor_sync(0xFFFFFFFF, s1, 16);
        if (lane < 4) {
            spart[d0 * 2 + wm] = s0;
            spart[(d0 + 1) * 2 + wm] = s1;
        }
    }
    __syncthreads();
    if (tid < 64)
        g_part[((size_t)(b * D + tid)) * 256 + mblk] = spart[tid * 2] + spart[tid * 2 + 1];
    // coalesced bf16 e-store: 512 x 16B items (64 rows x 128B)
#pragma unroll
    for (int k = 0; k < 2; k++) {
        int idx = tid + k * 256;                 // 0..511
        int row = idx >> 3, ch = idx & 7;
        uint4 vv = *(uint4*)(ztb + row * 144 + ch * 16);
        *(uint4*)((char*)g_ebf + ((size_t)(b * D + row) * NPIX + pix0) * 2 + ch * 16) = vv;
    }
}

// ---------------------------------------------------------------------------
// K2: rowinv (256 partials/row) + per-batch W2' = W2 * ri[d] planes.
// ---------------------------------------------------------------------------
__global__ __launch_bounds__(256) void rowinv_kernel()
{
    __shared__ float ri_s[64];
    __shared__ float red[256];
    int b = blockIdx.x, tid = threadIdx.x;
    int r = tid >> 2, qq = tid & 3;
    float s = 0.f;
#pragma unroll
    for (int i = 0; i < 64; i++)
        s += g_part[((size_t)(b * D + r)) * 256 + qq * 64 + i];
    red[tid] = s;
    __syncthreads();
    if (qq == 0) {
        float t = red[tid] + red[tid + 1] + red[tid + 2] + red[tid + 3];
        float ri = 1.f / t;
        ri_s[r] = ri;
        g_rowinv[b * D + r] = ri;
    }
    __syncthreads();
#pragma unroll
    for (int k = 0; k < 64; k++) {
        int idx = tid + k * 256;
        int c = idx >> 6, d = idx & 63;
        float wv = g_W2f[idx] * ri_s[d];
        __nv_bfloat16 hi, lo; split_bf16(wv, hi, lo);
        g_W2b[(size_t)b * 36864 + c * 72 + d] = hi;
        g_W2b[(size_t)b * 36864 + 18432 + c * 72 + d] = lo;
    }
}

// ---------------------------------------------------------------------------
// K3: out = relu(W2' @ e * scale + bias2 + x); scale = 1/(1e-9 + colsum(ri*e)).
// (unchanged from R11: 128 pix x 64 c, bf16 A, 4 CTAs/SM)
// ---------------------------------------------------------------------------
#define K3_A  0
#define K3_W  17408
#define K3_RI (K3_W + 18432)
#define K3_B2 (K3_RI + 256)
#define K3_CS (K3_B2 + 256)
#define K3_SC (K3_CS + 2048)
#define K3_SMEM (K3_SC + 512)

__global__ __launch_bounds__(256, 4) void output_kernel(const float* __restrict__ x,
                                                        float* __restrict__ out)
{
    extern __shared__ char sh[];
    uint32_t sb = smem_u32(sh);
    float* ri_s = (float*)(sh + K3_RI);
    float* b2_s = (float*)(sh + K3_B2);
    float* cs   = (float*)(sh + K3_CS);
    float* sc_s = (float*)(sh + K3_SC);
    int tid = threadIdx.x, w = tid >> 5, lane = tid & 31;
    int b = blockIdx.y;
    int cblk = blockIdx.x & 3, pixblk = blockIdx.x >> 2;
    int pix0 = pixblk * 128, cb0 = cblk * 64;

#pragma unroll
    for (int k = 0; k < 4; k++) {
        int idx = tid + k * 256;
        int d = idx >> 4, ch = idx & 15;
        cp16(sb + K3_A + d * 272 + ch * 16,
             (const char*)g_ebf + ((size_t)(b * D + d) * NPIX + pix0) * 2 + ch * 16);
    }
#pragma unroll
    for (int k = 0; k < 5; k++) {
        int idx = tid + k * 256;
        if (idx < 1152) {
            int plane = idx / 576, r = idx % 576;
            cp16(sb + K3_W + plane * 9216 + r * 16,
                 (const char*)g_W2b + (size_t)b * 73728 + plane * 36864 + cb0 * 144 + r * 16);
        }
    }
    cp_commit();
    if (tid < 64) {
        ri_s[tid] = g_rowinv[b * D + tid];
        b2_s[tid] = g_bias2[cb0 + tid];
    }
    cp_wait0();
    __syncthreads();

    // colsum over d of ri*e -> per-pixel scale (bf16x2 vectorized)
    {
        int pair = tid & 63;
        int dg = tid >> 6;
        float s0 = 0.f, s1 = 0.f;
#pragma unroll
        for (int j = 0; j < 16; j++) {
            int d = dg * 16 + j;
            __nv_bfloat162 e2 = *(const __nv_bfloat162*)(sh + K3_A + d * 272 + pair * 4);
            float ri = ri_s[d];
            s0 = fmaf(__bfloat162float(e2.x), ri, s0);
            s1 = fmaf(__bfloat162float(e2.y), ri, s1);
        }
        cs[dg * 128 + pair * 2]     = s0;
        cs[dg * 128 + pair * 2 + 1] = s1;
    }
    __syncthreads();
    if (tid < 128)
        sc_s[tid] = 1.f / (1e-9f + cs[tid] + cs[128 + tid] + cs[256 + tid] + cs[384 + tid]);
    __syncthreads();

    int wm = w & 3, wq = w >> 2;
    int m0 = wm * 32, n0 = wq * 32;
    uint32_t a_k = (lane & 7) + ((lane >> 4) << 3);
    uint32_t a_mo = ((lane >> 3) & 1) * 8;
    uint32_t b_row = lane & 15;
    uint32_t b_co = (lane >> 4) << 4;

    float acc[2][4][4];
#pragma unroll
    for (int t = 0; t < 2; t++)
#pragma unroll
        for (int q = 0; q < 4; q++)
#pragma unroll
            for (int i = 0; i < 4; i++) acc[t][q][i] = 0.f;

#pragma unroll
    for (int kk = 0; kk < 4; kk++) {
        uint32_t ah[2][4];
#pragma unroll
        for (int t = 0; t < 2; t++) {
            uint32_t off = (kk * 16 + a_k) * 272 + (m0 + t * 16 + a_mo) * 2;
            ldm_x4t(sb + K3_A + off, ah[t]);
        }
#pragma unroll
        for (int q = 0; q < 2; q++) {
            uint32_t off = (n0 + q * 16 + b_row) * 144 + kk * 32 + b_co;
            uint32_t bh[4], bl[4];
            ldm_x4(sb + K3_W + off, bh);
            ldm_x4(sb + K3_W + 9216 + off, bl);
#pragma unroll
            for (int t = 0; t < 2; t++) {
                mma_bf16(acc[t][q * 2], ah[t], bh[0], bh[2]);
                mma_bf16(acc[t][q * 2], ah[t], bl[0], bl[2]);
                mma_bf16(acc[t][q * 2 + 1], ah[t], bh[1], bh[3]);
                mma_bf16(acc[t][q * 2 + 1], ah[t], bl[1], bl[3]);
            }
        }
    }

    __syncthreads();
    float* zt = (float*)sh;
    {
        int clb = n0 + (lane & 3) * 2;
        int plocal = m0 + (lane >> 2);
#pragma unroll
        for (int t = 0; t < 2; t++) {
            int p0 = plocal + t * 16, p1 = p0 + 8;
#pragma unroll
            for (int q = 0; q < 4; q++) {
                int cl = clb + q * 8;
                zt[cl * 128 + p0]       = acc[t][q][0];
                zt[(cl + 1) * 128 + p0] = acc[t][q][1];
                zt[cl * 128 + p1]       = acc[t][q][2];
                zt[(cl + 1) * 128 + p1] = acc[t][q][3];
            }
        }
    }
    __syncthreads();

#pragma unroll
    for (int k = 0; k < 8; k++) {
        int idx = tid + k * 256;
        int row = idx >> 5, col = idx & 31;
        float4 z4 = ((const float4*)zt)[row * 32 + col];
        float4 sc4 = *(const float4*)(sc_s + col * 4);
        float bb = b2_s[row];
        size_t go = ((size_t)(b * C + cb0 + row)) * NPIX + pix0 + col * 4;
        float4 x4 = *(const float4*)(x + go);
        float4 o;
        o.x = fmaxf(fmaf(z4.x, sc4.x, bb) + x4.x, 0.f);
        o.y = fmaxf(fmaf(z4.y, sc4.y, bb) + x4.y, 0.f);
        o.z = fmaxf(fmaf(z4.z, sc4.z, bb) + x4.z, 0.f);
        o.w = fmaxf(fmaf(z4.w, sc4.w, bb) + x4.w, 0.f);
        *(float4*)(out + go) = o;
    }
}

// ---------------------------------------------------------------------------
extern "C" void kernel_launch(void* const* d_in, const int* in_sizes, int n_in,
                              void* d_out, int out_size)
{
    const float* x       = (const float*)d_in[0];
    const float* conv1_w = (const float*)d_in[1];
    const float* conv1_b = (const float*)d_in[2];
    const float* mk_w    = (const float*)d_in[3];
    const float* mv_w    = (const float*)d_in[4];
    const float* conv2_w = (const float*)d_in[5];
    const float* gamma   = (const float*)d_in[6];
    const float* beta    = (const float*)d_in[7];
    const float* mean    = (const float*)d_in[8];
    const float* var     = (const float*)d_in[9];
    float* out = (float*)d_out;

    cudaFuncSetAttribute(logits_kernel, cudaFuncAttributeMaxDynamicSharedMemorySize, K1_SMEM);
    cudaFuncSetAttribute(output_kernel, cudaFuncAttributeMaxDynamicSharedMemorySize, K3_SMEM);

    prep_kernel<<<130, 256>>>(conv1_w, conv1_b, mk_w, mv_w, conv2_w,
                              gamma, beta, mean, var);

    dim3 g1(NPIX / 64, BATCH);
    logits_kernel<<<g1, 256, K1_SMEM>>>(x);

    rowinv_kernel<<<BATCH, 256>>>();

    dim3 g3((NPIX / 128) * 4, BATCH);
    output_kernel<<<g3, 256, K3_SMEM>>>(x, out);
}

// round 14
// speedup vs baseline: 1.0780x; 1.0649x over previous
#include <cuda_runtime.h>
#include <cuda_bf16.h>
#include <cstdint>

#define BATCH 16
#define C 256
#define D 64
#define NPIX 16384

// ---------------- device scratch (no runtime allocation) -------------------
__device__ __nv_bfloat16 g_ebf[(size_t)BATCH * D * NPIX];  // exp(logits), bf16, 32MB
__device__ float g_part[BATCH * D * 128];
__device__ float g_rowinv[BATCH * D];
__device__ __nv_bfloat16 g_W1p[4 * 2 * 64 * 72];           // [ck][plane][d][72] padded
__device__ float g_W2f[C * D];                             // fp32 bn-folded W2 [c][d]
__device__ __nv_bfloat16 g_W2b[BATCH * 2 * 256 * 72];      // per-batch W2*ri hi/lo planes
__device__ float g_b1[D];
__device__ float g_bias2[C];

// ---------------- helpers ---------------------------------------------------
__device__ __forceinline__ uint32_t smem_u32(const void* p) {
    uint32_t a;
    asm("{ .reg .u64 t; cvta.to.shared.u64 t, %1; cvt.u32.u64 %0, t; }" : "=r"(a) : "l"(p));
    return a;
}
__device__ __forceinline__ void ldm_x4(uint32_t addr, uint32_t* r) {
    asm volatile("ldmatrix.sync.aligned.m8n8.x4.shared.b16 {%0,%1,%2,%3}, [%4];"
        : "=r"(r[0]), "=r"(r[1]), "=r"(r[2]), "=r"(r[3]) : "r"(addr));
}
__device__ __forceinline__ void ldm_x4t(uint32_t addr, uint32_t* r) {
    asm volatile("ldmatrix.sync.aligned.m8n8.x4.trans.shared.b16 {%0,%1,%2,%3}, [%4];"
        : "=r"(r[0]), "=r"(r[1]), "=r"(r[2]), "=r"(r[3]) : "r"(addr));
}
__device__ __forceinline__ void mma_bf16(float* d, const uint32_t* a, uint32_t b0, uint32_t b1) {
    asm volatile(
        "mma.sync.aligned.m16n8k16.row.col.f32.bf16.bf16.f32 "
        "{%0,%1,%2,%3}, {%4,%5,%6,%7}, {%8,%9}, {%0,%1,%2,%3};"
        : "+f"(d[0]), "+f"(d[1]), "+f"(d[2]), "+f"(d[3])
        : "r"(a[0]), "r"(a[1]), "r"(a[2]), "r"(a[3]), "r"(b0), "r"(b1));
}
__device__ __forceinline__ void cp16(uint32_t dst, const void* src) {
    asm volatile("cp.async.ca.shared.global [%0], [%1], 16;" :: "r"(dst), "l"(src));
}
__device__ __forceinline__ void cp_commit() { asm volatile("cp.async.commit_group;"); }
__device__ __forceinline__ void cp_wait0() { asm volatile("cp.async.wait_group 0;" ::: "memory"); }

// exp via FMA-pipe polynomial (no MUFU); rel err ~2e-6
__device__ __forceinline__ float fexp(float v) {
    float t = v * 1.44269504f;
    t = fminf(fmaxf(t, -120.f), 120.f);
    float r = rintf(t);
    float f = t - r;
    float q = 0.0013333558f;
    q = fmaf(q, f, 0.0096181291f);
    q = fmaf(q, f, 0.0555041087f);
    q = fmaf(q, f, 0.2402265069f);
    q = fmaf(q, f, 0.6931471806f);
    q = fmaf(q, f, 1.0f);
    return __int_as_float(((int)r + 127) << 23) * q;
}
__device__ __forceinline__ void split_bf16(float v, __nv_bfloat16& hi, __nv_bfloat16& lo) {
    hi = __float2bfloat16(v);
    lo = __float2bfloat16(v - __bfloat162float(hi));
}

// ---------------------------------------------------------------------------
// K0: fold weights + BN.  W1 -> padded hi/lo planes; W2 -> fp32 [c][d].
// ---------------------------------------------------------------------------
__global__ __launch_bounds__(256) void prep_kernel(
    const float* __restrict__ conv1_w, const float* __restrict__ conv1_b,
    const float* __restrict__ mk_w,    const float* __restrict__ mv_w,
    const float* __restrict__ conv2_w, const float* __restrict__ bn_gamma,
    const float* __restrict__ bn_beta, const float* __restrict__ bn_mean,
    const float* __restrict__ bn_var)
{
    int gid = blockIdx.x * blockDim.x + threadIdx.x;
    if (gid < D * C) {
        int d = gid >> 8, c = gid & 255;
        float s = 0.f;
        for (int o = 0; o < C; o++)
            s = fmaf(mk_w[d * C + o], conv1_w[o * C + c], s);
        __nv_bfloat16 hi, lo; split_bf16(s, hi, lo);
        int ck = c >> 6, cl = c & 63;
        g_W1p[ck * 9216 + d * 72 + cl] = hi;
        g_W1p[ck * 9216 + 4608 + d * 72 + cl] = lo;
    } else if (gid < 2 * D * C) {
        int j = gid - D * C;
        int c = j >> 6, d = j & 63;
        float inv = bn_gamma[c] * rsqrtf(bn_var[c] + 1e-5f);
        float s = 0.f;
        for (int cp = 0; cp < C; cp++)
            s = fmaf(conv2_w[c * C + cp], mv_w[cp * D + d], s);
        g_W2f[c * D + d] = s * inv;
    } else if (gid < 2 * D * C + D) {
        int d = gid - 2 * D * C;
        float s = 0.f;
        for (int o = 0; o < C; o++)
            s = fmaf(mk_w[d * C + o], conv1_b[o], s);
        g_b1[d] = s;
    } else if (gid < 2 * D * C + D + C) {
        int c = gid - 2 * D * C - D;
        float inv = bn_gamma[c] * rsqrtf(bn_var[c] + 1e-5f);
        g_bias2[c] = bn_beta[c] - bn_mean[c] * inv;
    }
}

// ---------------------------------------------------------------------------
// K1: e = exp(W1 @ x + b1) -> bf16, + per-block row partial sums.
// R11 structure (128 pix x 64 d, 4 chunks of 64, single-buffered, 4 CTAs/SM)
// with W staging via cp.async (overlaps the X DRAM loads).
// ---------------------------------------------------------------------------
#define K1_XH 0                          // 17408
#define K1_W  17408                      // 18432 (hi 9216 + lo 9216)
#define K1_B1 35840                      // 256
#define K1_SPART 36096                   // 1024
#define K1_SMEM 37120

__global__ __launch_bounds__(256, 4) void logits_kernel(const float* __restrict__ x)
{
    extern __shared__ char sh[];
    uint32_t sb = smem_u32(sh);
    float* b1s   = (float*)(sh + K1_B1);
    float* spart = (float*)(sh + K1_SPART);
    int tid = threadIdx.x, w = tid >> 5, lane = tid & 31;
    int b = blockIdx.y, mblk = blockIdx.x, pix0 = mblk * 128;

    if (tid < 64) b1s[tid] = g_b1[tid];

    int wm = w & 3, wq = w >> 2;
    int m0 = wm * 32, n0 = wq * 32;
    uint32_t a_k = (lane & 7) + ((lane >> 4) << 3);
    uint32_t a_mo = ((lane >> 3) & 1) * 8;
    uint32_t b_row = lane & 15;
    uint32_t b_co = (lane >> 4) << 4;
    int p2 = (tid & 63) * 2;
    int cg = tid >> 6;

    float acc[2][4][4];
#pragma unroll
    for (int t = 0; t < 2; t++)
#pragma unroll
        for (int q = 0; q < 4; q++)
#pragma unroll
            for (int i = 0; i < 4; i++) acc[t][q][i] = 0.f;

    for (int ck = 0; ck < 4; ck++) {
        // stage W chunk (hi+lo planes, 1152 x 16B) via cp.async — completes
        // under the X staging LDGs below
#pragma unroll
        for (int k = 0; k < 5; k++) {
            int idx = tid + k * 256;
            if (idx < 1152)
                cp16(sb + K1_W + idx * 16,
                     (const char*)g_W1p + ck * 18432 + idx * 16);
        }
        cp_commit();
        // stage x chunk -> single bf16 plane, K-major [c][pix]
        {
            const float* xp = x + ((size_t)b * C + ck * 64 + cg * 16) * NPIX + pix0 + p2;
            char* xh = sh + K1_XH + (size_t)cg * 16 * 272 + p2 * 2;
#pragma unroll
            for (int jb = 0; jb < 2; jb++) {
                float2 v[8];
#pragma unroll
                for (int u = 0; u < 8; u++)
                    v[u] = *(const float2*)(xp + (size_t)(jb * 8 + u) * NPIX);
#pragma unroll
                for (int u = 0; u < 8; u++) {
                    int j = jb * 8 + u;
                    __nv_bfloat162 hp;
                    hp.x = __float2bfloat16(v[u].x);
                    hp.y = __float2bfloat16(v[u].y);
                    *(__nv_bfloat162*)(xh + j * 272) = hp;
                }
            }
        }
        cp_wait0();
        __syncthreads();

#pragma unroll
        for (int kk = 0; kk < 4; kk++) {
            uint32_t ah[2][4];
#pragma unroll
            for (int t = 0; t < 2; t++) {
                uint32_t off = (kk * 16 + a_k) * 272 + (m0 + t * 16 + a_mo) * 2;
                ldm_x4t(sb + K1_XH + off, ah[t]);
            }
            uint32_t bh[2][4], bl[2][4];
#pragma unroll
            for (int q = 0; q < 2; q++) {
                uint32_t off = (n0 + q * 16 + b_row) * 144 + kk * 32 + b_co;
                ldm_x4(sb + K1_W + off, bh[q]);
                ldm_x4(sb + K1_W + 9216 + off, bl[q]);
            }
#pragma unroll
            for (int t = 0; t < 2; t++)
#pragma unroll
                for (int q = 0; q < 2; q++) {
                    mma_bf16(acc[t][q * 2], ah[t], bh[q][0], bh[q][2]);
                    mma_bf16(acc[t][q * 2], ah[t], bl[q][0], bl[q][2]);
                    mma_bf16(acc[t][q * 2 + 1], ah[t], bh[q][1], bh[q][3]);
                    mma_bf16(acc[t][q * 2 + 1], ah[t], bl[q][1], bl[q][3]);
                }
        }
        __syncthreads();
    }

    // epilogue: exp -> bf16 z-tile [d][128 pix] in smem, + row partials
    __nv_bfloat16* ztb = (__nv_bfloat16*)(sh + K1_XH);
    int dbase = n0 + (lane & 3) * 2;
    int plocal = m0 + (lane >> 2);
#pragma unroll
    for (int q = 0; q < 4; q++) {
        int d0 = dbase + q * 8;
        float bb0 = b1s[d0], bb1 = b1s[d0 + 1];
        float s0 = 0.f, s1 = 0.f;
#pragma unroll
        for (int t = 0; t < 2; t++) {
            int p0 = plocal + t * 16, p1 = p0 + 8;
            float v00 = fexp(acc[t][q][0] + bb0); ztb[d0 * 128 + p0] = __float2bfloat16(v00);
            float v01 = fexp(acc[t][q][1] + bb1); ztb[(d0 + 1) * 128 + p0] = __float2bfloat16(v01);
            float v02 = fexp(acc[t][q][2] + bb0); ztb[d0 * 128 + p1] = __float2bfloat16(v02);
            float v03 = fexp(acc[t][q][3] + bb1); ztb[(d0 + 1) * 128 + p1] = __float2bfloat16(v03);
            s0 += v00 + v02; s1 += v01 + v03;
        }
        s0 += __shfl_xor_sync(0xFFFFFFFF, s0, 4);
        s0 += __shfl_xor_sync(0xFFFFFFFF, s0, 8);
        s0 += __shfl_xor_sync(0xFFFFFFFF, s0, 16);
        s1 += __shfl_xor_sync(0xFFFFFFFF, s1, 4);
        s1 += __shfl_xor_sync(0xFFFFFFFF, s1, 8);
        s1 += __shfl_xor_sync(0xFFFFFFFF, s1, 16);
        if (lane < 4) {
            spart[d0 * 4 + wm] = s0;
            spart[(d0 + 1) * 4 + wm] = s1;
        }
    }
    __syncthreads();
    if (tid < 64) {
        float s = spart[tid * 4] + spart[tid * 4 + 1] + spart[tid * 4 + 2] + spart[tid * 4 + 3];
        g_part[(b * D + tid) * 128 + mblk] = s;
    }
    // coalesced bf16 store: 1024 x 16B items
#pragma unroll
    for (int k = 0; k < 4; k++) {
        int idx = tid + k * 256;
        int row = idx >> 4, ch = idx & 15;
        uint4 v = *(uint4*)((char*)ztb + row * 256 + ch * 16);
        *(uint4*)((char*)g_ebf + ((size_t)(b * D + row) * NPIX + pix0) * 2 + ch * 16) = v;
    }
}

// ---------------------------------------------------------------------------
// K2: rowinv + per-batch W2' = W2 * ri[d] -> padded bf16 hi/lo planes.
// ---------------------------------------------------------------------------
__global__ __launch_bounds__(256) void rowinv_kernel()
{
    __shared__ float ri_s[64];
    __shared__ float red[256];
    int b = blockIdx.x, tid = threadIdx.x;
    int r = tid >> 2, qq = tid & 3;
    float s = 0.f;
#pragma unroll
    for (int i = 0; i < 32; i++)
        s += g_part[(b * D + r) * 128 + qq * 32 + i];
    red[tid] = s;
    __syncthreads();
    if (qq == 0) {
        float t = red[tid] + red[tid + 1] + red[tid + 2] + red[tid + 3];
        float ri = 1.f / t;
        ri_s[r] = ri;
        g_rowinv[b * D + r] = ri;
    }
    __syncthreads();
#pragma unroll
    for (int k = 0; k < 64; k++) {
        int idx = tid + k * 256;
        int c = idx >> 6, d = idx & 63;
        float wv = g_W2f[idx] * ri_s[d];
        __nv_bfloat16 hi, lo; split_bf16(wv, hi, lo);
        g_W2b[(size_t)b * 36864 + c * 72 + d] = hi;
        g_W2b[(size_t)b * 36864 + 18432 + c * 72 + d] = lo;
    }
}

// ---------------------------------------------------------------------------
// K3: out = relu(W2' @ e * scale + bias2 + x); scale = 1/(1e-9 + colsum(ri*e)).
// (unchanged from R11: 128 pix x 64 c, bf16 A, 4 CTAs/SM)
// ---------------------------------------------------------------------------
#define K3_A  0
#define K3_W  17408
#define K3_RI (K3_W + 18432)
#define K3_B2 (K3_RI + 256)
#define K3_CS (K3_B2 + 256)
#define K3_SC (K3_CS + 2048)
#define K3_SMEM (K3_SC + 512)

__global__ __launch_bounds__(256, 4) void output_kernel(const float* __restrict__ x,
                                                        float* __restrict__ out)
{
    extern __shared__ char sh[];
    uint32_t sb = smem_u32(sh);
    float* ri_s = (float*)(sh + K3_RI);
    float* b2_s = (float*)(sh + K3_B2);
    float* cs   = (float*)(sh + K3_CS);
    float* sc_s = (float*)(sh + K3_SC);
    int tid = threadIdx.x, w = tid >> 5, lane = tid & 31;
    int b = blockIdx.y;
    int cblk = blockIdx.x & 3, pixblk = blockIdx.x >> 2;
    int pix0 = pixblk * 128, cb0 = cblk * 64;

#pragma unroll
    for (int k = 0; k < 4; k++) {
        int idx = tid + k * 256;
        int d = idx >> 4, ch = idx & 15;
        cp16(sb + K3_A + d * 272 + ch * 16,
             (const char*)g_ebf + ((size_t)(b * D + d) * NPIX + pix0) * 2 + ch * 16);
    }
#pragma unroll
    for (int k = 0; k < 5; k++) {
        int idx = tid + k * 256;
        if (idx < 1152) {
            int plane = idx / 576, r = idx % 576;
            cp16(sb + K3_W + plane * 9216 + r * 16,
                 (const char*)g_W2b + (size_t)b * 73728 + plane * 36864 + cb0 * 144 + r * 16);
        }
    }
    cp_commit();
    if (tid < 64) {
        ri_s[tid] = g_rowinv[b * D + tid];
        b2_s[tid] = g_bias2[cb0 + tid];
    }
    cp_wait0();
    __syncthreads();

    // colsum over d of ri*e -> per-pixel scale (bf16x2 vectorized)
    {
        int pair = tid & 63;
        int dg = tid >> 6;
        float s0 = 0.f, s1 = 0.f;
#pragma unroll
        for (int j = 0; j < 16; j++) {
            int d = dg * 16 + j;
            __nv_bfloat162 e2 = *(const __nv_bfloat162*)(sh + K3_A + d * 272 + pair * 4);
            float ri = ri_s[d];
            s0 = fmaf(__bfloat162float(e2.x), ri, s0);
            s1 = fmaf(__bfloat162float(e2.y), ri, s1);
        }
        cs[dg * 128 + pair * 2]     = s0;
        cs[dg * 128 + pair * 2 + 1] = s1;
    }
    __syncthreads();
    if (tid < 128)
        sc_s[tid] = 1.f / (1e-9f + cs[tid] + cs[128 + tid] + cs[256 + tid] + cs[384 + tid]);
    __syncthreads();

    int wm = w & 3, wq = w >> 2;
    int m0 = wm * 32, n0 = wq * 32;
    uint32_t a_k = (lane & 7) + ((lane >> 4) << 3);
    uint32_t a_mo = ((lane >> 3) & 1) * 8;
    uint32_t b_row = lane & 15;
    uint32_t b_co = (lane >> 4) << 4;

    float acc[2][4][4];
#pragma unroll
    for (int t = 0; t < 2; t++)
#pragma unroll
        for (int q = 0; q < 4; q++)
#pragma unroll
            for (int i = 0; i < 4; i++) acc[t][q][i] = 0.f;

#pragma unroll
    for (int kk = 0; kk < 4; kk++) {
        uint32_t ah[2][4];
#pragma unroll
        for (int t = 0; t < 2; t++) {
            uint32_t off = (kk * 16 + a_k) * 272 + (m0 + t * 16 + a_mo) * 2;
            ldm_x4t(sb + K3_A + off, ah[t]);
        }
#pragma unroll
        for (int q = 0; q < 2; q++) {
            uint32_t off = (n0 + q * 16 + b_row) * 144 + kk * 32 + b_co;
            uint32_t bh[4], bl[4];
            ldm_x4(sb + K3_W + off, bh);
            ldm_x4(sb + K3_W + 9216 + off, bl);
#pragma unroll
            for (int t = 0; t < 2; t++) {
                mma_bf16(acc[t][q * 2], ah[t], bh[0], bh[2]);
                mma_bf16(acc[t][q * 2], ah[t], bl[0], bl[2]);
                mma_bf16(acc[t][q * 2 + 1], ah[t], bh[1], bh[3]);
                mma_bf16(acc[t][q * 2 + 1], ah[t], bl[1], bl[3]);
            }
        }
    }

    __syncthreads();
    float* zt = (float*)sh;
    {
        int clb = n0 + (lane & 3) * 2;
        int plocal = m0 + (lane >> 2);
#pragma unroll
        for (int t = 0; t < 2; t++) {
            int p0 = plocal + t * 16, p1 = p0 + 8;
#pragma unroll
            for (int q = 0; q < 4; q++) {
                int cl = clb + q * 8;
                zt[cl * 128 + p0]       = acc[t][q][0];
                zt[(cl + 1) * 128 + p0] = acc[t][q][1];
                zt[cl * 128 + p1]       = acc[t][q][2];
                zt[(cl + 1) * 128 + p1] = acc[t][q][3];
            }
        }
    }
    __syncthreads();

#pragma unroll
    for (int k = 0; k < 8; k++) {
        int idx = tid + k * 256;
        int row = idx >> 5, col = idx & 31;
        float4 z4 = ((const float4*)zt)[row * 32 + col];
        float4 sc4 = *(const float4*)(sc_s + col * 4);
        float bb = b2_s[row];
        size_t go = ((size_t)(b * C + cb0 + row)) * NPIX + pix0 + col * 4;
        float4 x4 = *(const float4*)(x + go);
        float4 o;
        o.x = fmaxf(fmaf(z4.x, sc4.x, bb) + x4.x, 0.f);
        o.y = fmaxf(fmaf(z4.y, sc4.y, bb) + x4.y, 0.f);
        o.z = fmaxf(fmaf(z4.z, sc4.z, bb) + x4.z, 0.f);
        o.w = fmaxf(fmaf(z4.w, sc4.w, bb) + x4.w, 0.f);
        *(float4*)(out + go) = o;
    }
}

// ---------------------------------------------------------------------------
extern "C" void kernel_launch(void* const* d_in, const int* in_sizes, int n_in,
                              void* d_out, int out_size)
{
    const float* x       = (const float*)d_in[0];
    const float* conv1_w = (const float*)d_in[1];
    const float* conv1_b = (const float*)d_in[2];
    const float* mk_w    = (const float*)d_in[3];
    const float* mv_w    = (const float*)d_in[4];
    const float* conv2_w = (const float*)d_in[5];
    const float* gamma   = (const float*)d_in[6];
    const float* beta    = (const float*)d_in[7];
    const float* mean    = (const float*)d_in[8];
    const float* var     = (const float*)d_in[9];
    float* out = (float*)d_out;

    cudaFuncSetAttribute(logits_kernel, cudaFuncAttributeMaxDynamicSharedMemorySize, K1_SMEM);
    cudaFuncSetAttribute(output_kernel, cudaFuncAttributeMaxDynamicSharedMemorySize, K3_SMEM);

    prep_kernel<<<130, 256>>>(conv1_w, conv1_b, mk_w, mv_w, conv2_w,
                              gamma, beta, mean, var);

    dim3 g1(NPIX / 128, BATCH);
    logits_kernel<<<g1, 256, K1_SMEM>>>(x);

    rowinv_kernel<<<BATCH, 256>>>();

    dim3 g3((NPIX / 128) * 4, BATCH);
    output_kernel<<<g3, 256, K3_SMEM>>>(x, out);
}

// round 15
// speedup vs baseline: 1.1020x; 1.0222x over previous
#include <cuda_runtime.h>
#include <cuda_bf16.h>
#include <cstdint>

#define BATCH 16
#define C 256
#define D 64
#define NPIX 16384

// ---------------- device scratch (no runtime allocation) -------------------
__device__ __nv_bfloat16 g_ebf[(size_t)BATCH * D * NPIX];  // exp(logits), bf16, 32MB
__device__ float g_part[BATCH * D * 128];
__device__ float g_rowinv[BATCH * D];
__device__ __nv_bfloat16 g_W1p[4 * 2 * 64 * 72];           // [ck][plane][d][72] padded
__device__ float g_W2f[C * D];                             // fp32 bn-folded W2 [c][d]
__device__ __nv_bfloat16 g_W2b[BATCH * 2 * 256 * 72];      // per-batch W2*ri hi/lo planes
__device__ float g_b1[D];
__device__ float g_bias2[C];

// ---------------- helpers ---------------------------------------------------
__device__ __forceinline__ uint32_t smem_u32(const void* p) {
    uint32_t a;
    asm("{ .reg .u64 t; cvta.to.shared.u64 t, %1; cvt.u32.u64 %0, t; }" : "=r"(a) : "l"(p));
    return a;
}
__device__ __forceinline__ void ldm_x4(uint32_t addr, uint32_t* r) {
    asm volatile("ldmatrix.sync.aligned.m8n8.x4.shared.b16 {%0,%1,%2,%3}, [%4];"
        : "=r"(r[0]), "=r"(r[1]), "=r"(r[2]), "=r"(r[3]) : "r"(addr));
}
__device__ __forceinline__ void ldm_x4t(uint32_t addr, uint32_t* r) {
    asm volatile("ldmatrix.sync.aligned.m8n8.x4.trans.shared.b16 {%0,%1,%2,%3}, [%4];"
        : "=r"(r[0]), "=r"(r[1]), "=r"(r[2]), "=r"(r[3]) : "r"(addr));
}
__device__ __forceinline__ void mma_bf16(float* d, const uint32_t* a, uint32_t b0, uint32_t b1) {
    asm volatile(
        "mma.sync.aligned.m16n8k16.row.col.f32.bf16.bf16.f32 "
        "{%0,%1,%2,%3}, {%4,%5,%6,%7}, {%8,%9}, {%0,%1,%2,%3};"
        : "+f"(d[0]), "+f"(d[1]), "+f"(d[2]), "+f"(d[3])
        : "r"(a[0]), "r"(a[1]), "r"(a[2]), "r"(a[3]), "r"(b0), "r"(b1));
}
__device__ __forceinline__ void cp16(uint32_t dst, const void* src) {
    asm volatile("cp.async.ca.shared.global [%0], [%1], 16;" :: "r"(dst), "l"(src));
}
__device__ __forceinline__ void cp_commit() { asm volatile("cp.async.commit_group;"); }
__device__ __forceinline__ void cp_wait0() { asm volatile("cp.async.wait_group 0;" ::: "memory"); }

// exp via FMA-pipe polynomial (no MUFU); rel err ~2e-6
__device__ __forceinline__ float fexp(float v) {
    float t = v * 1.44269504f;
    t = fminf(fmaxf(t, -120.f), 120.f);
    float r = rintf(t);
    float f = t - r;
    float q = 0.0013333558f;
    q = fmaf(q, f, 0.0096181291f);
    q = fmaf(q, f, 0.0555041087f);
    q = fmaf(q, f, 0.2402265069f);
    q = fmaf(q, f, 0.6931471806f);
    q = fmaf(q, f, 1.0f);
    return __int_as_float(((int)r + 127) << 23) * q;
}
__device__ __forceinline__ void split_bf16(float v, __nv_bfloat16& hi, __nv_bfloat16& lo) {
    hi = __float2bfloat16(v);
    lo = __float2bfloat16(v - __bfloat162float(hi));
}

// ---------------------------------------------------------------------------
// K0: fold weights + BN.  W1 -> padded hi/lo planes; W2 -> fp32 [c][d].
// ---------------------------------------------------------------------------
__global__ __launch_bounds__(256) void prep_kernel(
    const float* __restrict__ conv1_w, const float* __restrict__ conv1_b,
    const float* __restrict__ mk_w,    const float* __restrict__ mv_w,
    const float* __restrict__ conv2_w, const float* __restrict__ bn_gamma,
    const float* __restrict__ bn_beta, const float* __restrict__ bn_mean,
    const float* __restrict__ bn_var)
{
    int gid = blockIdx.x * blockDim.x + threadIdx.x;
    if (gid < D * C) {
        int d = gid >> 8, c = gid & 255;
        float s = 0.f;
        for (int o = 0; o < C; o++)
            s = fmaf(mk_w[d * C + o], conv1_w[o * C + c], s);
        __nv_bfloat16 hi, lo; split_bf16(s, hi, lo);
        int ck = c >> 6, cl = c & 63;
        g_W1p[ck * 9216 + d * 72 + cl] = hi;
        g_W1p[ck * 9216 + 4608 + d * 72 + cl] = lo;
    } else if (gid < 2 * D * C) {
        int j = gid - D * C;
        int c = j >> 6, d = j & 63;
        float inv = bn_gamma[c] * rsqrtf(bn_var[c] + 1e-5f);
        float s = 0.f;
        for (int cp = 0; cp < C; cp++)
            s = fmaf(conv2_w[c * C + cp], mv_w[cp * D + d], s);
        g_W2f[c * D + d] = s * inv;
    } else if (gid < 2 * D * C + D) {
        int d = gid - 2 * D * C;
        float s = 0.f;
        for (int o = 0; o < C; o++)
            s = fmaf(mk_w[d * C + o], conv1_b[o], s);
        g_b1[d] = s;
    } else if (gid < 2 * D * C + D + C) {
        int c = gid - 2 * D * C - D;
        float inv = bn_gamma[c] * rsqrtf(bn_var[c] + 1e-5f);
        g_bias2[c] = bn_beta[c] - bn_mean[c] * inv;
    }
}

// ---------------------------------------------------------------------------
// K1: e = exp(W1 @ x + b1) -> bf16, + per-block row partial sums.
// R14 structure + float4 x staging (one 512B row per warp-iteration).
// ---------------------------------------------------------------------------
#define K1_XH 0                          // 17408
#define K1_W  17408                      // 18432 (hi 9216 + lo 9216)
#define K1_B1 35840                      // 256
#define K1_SPART 36096                   // 1024
#define K1_SMEM 37120

__global__ __launch_bounds__(256, 4) void logits_kernel(const float* __restrict__ x)
{
    extern __shared__ char sh[];
    uint32_t sb = smem_u32(sh);
    float* b1s   = (float*)(sh + K1_B1);
    float* spart = (float*)(sh + K1_SPART);
    int tid = threadIdx.x, w = tid >> 5, lane = tid & 31;
    int b = blockIdx.y, mblk = blockIdx.x, pix0 = mblk * 128;

    if (tid < 64) b1s[tid] = g_b1[tid];

    int wm = w & 3, wq = w >> 2;
    int m0 = wm * 32, n0 = wq * 32;
    uint32_t a_k = (lane & 7) + ((lane >> 4) << 3);
    uint32_t a_mo = ((lane >> 3) & 1) * 8;
    uint32_t b_row = lane & 15;
    uint32_t b_co = (lane >> 4) << 4;

    float acc[2][4][4];
#pragma unroll
    for (int t = 0; t < 2; t++)
#pragma unroll
        for (int q = 0; q < 4; q++)
#pragma unroll
            for (int i = 0; i < 4; i++) acc[t][q][i] = 0.f;

    for (int ck = 0; ck < 4; ck++) {
        // stage W chunk (hi+lo planes, 1152 x 16B) via cp.async — completes
        // under the X staging LDGs below
#pragma unroll
        for (int k = 0; k < 5; k++) {
            int idx = tid + k * 256;
            if (idx < 1152)
                cp16(sb + K1_W + idx * 16,
                     (const char*)g_W1p + ck * 18432 + idx * 16);
        }
        cp_commit();
        // stage x chunk -> single bf16 plane, K-major [c][pix]; float4 loads,
        // warp w covers rows w*8..w*8+7, lane covers pixels lane*4..lane*4+3
        {
            const float* xp = x + ((size_t)b * C + ck * 64 + w * 8) * NPIX + pix0 + lane * 4;
            char* xh = sh + K1_XH + (size_t)(w * 8) * 272 + lane * 8;
#pragma unroll
            for (int jb = 0; jb < 2; jb++) {
                float4 v[4];
#pragma unroll
                for (int u = 0; u < 4; u++)
                    v[u] = *(const float4*)(xp + (size_t)(jb * 4 + u) * NPIX);
#pragma unroll
                for (int u = 0; u < 4; u++) {
                    int j = jb * 4 + u;
                    __nv_bfloat162 lo2 = __floats2bfloat162_rn(v[u].x, v[u].y);
                    __nv_bfloat162 hi2 = __floats2bfloat162_rn(v[u].z, v[u].w);
                    uint2 pp;
                    pp.x = *(uint32_t*)&lo2;
                    pp.y = *(uint32_t*)&hi2;
                    *(uint2*)(xh + j * 272) = pp;
                }
            }
        }
        cp_wait0();
        __syncthreads();

#pragma unroll
        for (int kk = 0; kk < 4; kk++) {
            uint32_t ah[2][4];
#pragma unroll
            for (int t = 0; t < 2; t++) {
                uint32_t off = (kk * 16 + a_k) * 272 + (m0 + t * 16 + a_mo) * 2;
                ldm_x4t(sb + K1_XH + off, ah[t]);
            }
            uint32_t bh[2][4], bl[2][4];
#pragma unroll
            for (int q = 0; q < 2; q++) {
                uint32_t off = (n0 + q * 16 + b_row) * 144 + kk * 32 + b_co;
                ldm_x4(sb + K1_W + off, bh[q]);
                ldm_x4(sb + K1_W + 9216 + off, bl[q]);
            }
#pragma unroll
            for (int t = 0; t < 2; t++)
#pragma unroll
                for (int q = 0; q < 2; q++) {
                    mma_bf16(acc[t][q * 2], ah[t], bh[q][0], bh[q][2]);
                    mma_bf16(acc[t][q * 2], ah[t], bl[q][0], bl[q][2]);
                    mma_bf16(acc[t][q * 2 + 1], ah[t], bh[q][1], bh[q][3]);
                    mma_bf16(acc[t][q * 2 + 1], ah[t], bl[q][1], bl[q][3]);
                }
        }
        __syncthreads();
    }

    // epilogue: exp -> bf16 z-tile [d][128 pix] in smem, + row partials
    __nv_bfloat16* ztb = (__nv_bfloat16*)(sh + K1_XH);
    int dbase = n0 + (lane & 3) * 2;
    int plocal = m0 + (lane >> 2);
#pragma unroll
    for (int q = 0; q < 4; q++) {
        int d0 = dbase + q * 8;
        float bb0 = b1s[d0], bb1 = b1s[d0 + 1];
        float s0 = 0.f, s1 = 0.f;
#pragma unroll
        for (int t = 0; t < 2; t++) {
            int p0 = plocal + t * 16, p1 = p0 + 8;
            float v00 = fexp(acc[t][q][0] + bb0); ztb[d0 * 128 + p0] = __float2bfloat16(v00);
            float v01 = fexp(acc[t][q][1] + bb1); ztb[(d0 + 1) * 128 + p0] = __float2bfloat16(v01);
            float v02 = fexp(acc[t][q][2] + bb0); ztb[d0 * 128 + p1] = __float2bfloat16(v02);
            float v03 = fexp(acc[t][q][3] + bb1); ztb[(d0 + 1) * 128 + p1] = __float2bfloat16(v03);
            s0 += v00 + v02; s1 += v01 + v03;
        }
        s0 += __shfl_xor_sync(0xFFFFFFFF, s0, 4);
        s0 += __shfl_xor_sync(0xFFFFFFFF, s0, 8);
        s0 += __shfl_xor_sync(0xFFFFFFFF, s0, 16);
        s1 += __shfl_xor_sync(0xFFFFFFFF, s1, 4);
        s1 += __shfl_xor_sync(0xFFFFFFFF, s1, 8);
        s1 += __shfl_xor_sync(0xFFFFFFFF, s1, 16);
        if (lane < 4) {
            spart[d0 * 4 + wm] = s0;
            spart[(d0 + 1) * 4 + wm] = s1;
        }
    }
    __syncthreads();
    if (tid < 64) {
        float s = spart[tid * 4] + spart[tid * 4 + 1] + spart[tid * 4 + 2] + spart[tid * 4 + 3];
        g_part[(b * D + tid) * 128 + mblk] = s;
    }
    // coalesced bf16 store: 1024 x 16B items
#pragma unroll
    for (int k = 0; k < 4; k++) {
        int idx = tid + k * 256;
        int row = idx >> 4, ch = idx & 15;
        uint4 v = *(uint4*)((char*)ztb + row * 256 + ch * 16);
        *(uint4*)((char*)g_ebf + ((size_t)(b * D + row) * NPIX + pix0) * 2 + ch * 16) = v;
    }
}

// ---------------------------------------------------------------------------
// K2: rowinv + per-batch W2' = W2 * ri[d] -> padded bf16 hi/lo planes.
// ---------------------------------------------------------------------------
__global__ __launch_bounds__(256) void rowinv_kernel()
{
    __shared__ float ri_s[64];
    __shared__ float red[256];
    int b = blockIdx.x, tid = threadIdx.x;
    int r = tid >> 2, qq = tid & 3;
    float s = 0.f;
#pragma unroll
    for (int i = 0; i < 32; i++)
        s += g_part[(b * D + r) * 128 + qq * 32 + i];
    red[tid] = s;
    __syncthreads();
    if (qq == 0) {
        float t = red[tid] + red[tid + 1] + red[tid + 2] + red[tid + 3];
        float ri = 1.f / t;
        ri_s[r] = ri;
        g_rowinv[b * D + r] = ri;
    }
    __syncthreads();
#pragma unroll
    for (int k = 0; k < 64; k++) {
        int idx = tid + k * 256;
        int c = idx >> 6, d = idx & 63;
        float wv = g_W2f[idx] * ri_s[d];
        __nv_bfloat16 hi, lo; split_bf16(wv, hi, lo);
        g_W2b[(size_t)b * 36864 + c * 72 + d] = hi;
        g_W2b[(size_t)b * 36864 + 18432 + c * 72 + d] = lo;
    }
}

// ---------------------------------------------------------------------------
// K3: out = relu(W2' @ e * scale + bias2 + x); scale = 1/(1e-9 + colsum(ri*e)).
// (unchanged from R14: 128 pix x 64 c, bf16 A, 4 CTAs/SM)
// ---------------------------------------------------------------------------
#define K3_A  0
#define K3_W  17408
#define K3_RI (K3_W + 18432)
#define K3_B2 (K3_RI + 256)
#define K3_CS (K3_B2 + 256)
#define K3_SC (K3_CS + 2048)
#define K3_SMEM (K3_SC + 512)

__global__ __launch_bounds__(256, 4) void output_kernel(const float* __restrict__ x,
                                                        float* __restrict__ out)
{
    extern __shared__ char sh[];
    uint32_t sb = smem_u32(sh);
    float* ri_s = (float*)(sh + K3_RI);
    float* b2_s = (float*)(sh + K3_B2);
    float* cs   = (float*)(sh + K3_CS);
    float* sc_s = (float*)(sh + K3_SC);
    int tid = threadIdx.x, w = tid >> 5, lane = tid & 31;
    int b = blockIdx.y;
    int cblk = blockIdx.x & 3, pixblk = blockIdx.x >> 2;
    int pix0 = pixblk * 128, cb0 = cblk * 64;

#pragma unroll
    for (int k = 0; k < 4; k++) {
        int idx = tid + k * 256;
        int d = idx >> 4, ch = idx & 15;
        cp16(sb + K3_A + d * 272 + ch * 16,
             (const char*)g_ebf + ((size_t)(b * D + d) * NPIX + pix0) * 2 + ch * 16);
    }
#pragma unroll
    for (int k = 0; k < 5; k++) {
        int idx = tid + k * 256;
        if (idx < 1152) {
            int plane = idx / 576, r = idx % 576;
            cp16(sb + K3_W + plane * 9216 + r * 16,
                 (const char*)g_W2b + (size_t)b * 73728 + plane * 36864 + cb0 * 144 + r * 16);
        }
    }
    cp_commit();
    if (tid < 64) {
        ri_s[tid] = g_rowinv[b * D + tid];
        b2_s[tid] = g_bias2[cb0 + tid];
    }
    cp_wait0();
    __syncthreads();

    // colsum over d of ri*e -> per-pixel scale (bf16x2 vectorized)
    {
        int pair = tid & 63;
        int dg = tid >> 6;
        float s0 = 0.f, s1 = 0.f;
#pragma unroll
        for (int j = 0; j < 16; j++) {
            int d = dg * 16 + j;
            __nv_bfloat162 e2 = *(const __nv_bfloat162*)(sh + K3_A + d * 272 + pair * 4);
            float ri = ri_s[d];
            s0 = fmaf(__bfloat162float(e2.x), ri, s0);
            s1 = fmaf(__bfloat162float(e2.y), ri, s1);
        }
        cs[dg * 128 + pair * 2]     = s0;
        cs[dg * 128 + pair * 2 + 1] = s1;
    }
    __syncthreads();
    if (tid < 128)
        sc_s[tid] = 1.f / (1e-9f + cs[tid] + cs[128 + tid] + cs[256 + tid] + cs[384 + tid]);
    __syncthreads();

    int wm = w & 3, wq = w >> 2;
    int m0 = wm * 32, n0 = wq * 32;
    uint32_t a_k = (lane & 7) + ((lane >> 4) << 3);
    uint32_t a_mo = ((lane >> 3) & 1) * 8;
    uint32_t b_row = lane & 15;
    uint32_t b_co = (lane >> 4) << 4;

    float acc[2][4][4];
#pragma unroll
    for (int t = 0; t < 2; t++)
#pragma unroll
        for (int q = 0; q < 4; q++)
#pragma unroll
            for (int i = 0; i < 4; i++) acc[t][q][i] = 0.f;

#pragma unroll
    for (int kk = 0; kk < 4; kk++) {
        uint32_t ah[2][4];
#pragma unroll
        for (int t = 0; t < 2; t++) {
            uint32_t off = (kk * 16 + a_k) * 272 + (m0 + t * 16 + a_mo) * 2;
            ldm_x4t(sb + K3_A + off, ah[t]);
        }
#pragma unroll
        for (int q = 0; q < 2; q++) {
            uint32_t off = (n0 + q * 16 + b_row) * 144 + kk * 32 + b_co;
            uint32_t bh[4], bl[4];
            ldm_x4(sb + K3_W + off, bh);
            ldm_x4(sb + K3_W + 9216 + off, bl);
#pragma unroll
            for (int t = 0; t < 2; t++) {
                mma_bf16(acc[t][q * 2], ah[t], bh[0], bh[2]);
                mma_bf16(acc[t][q * 2], ah[t], bl[0], bl[2]);
                mma_bf16(acc[t][q * 2 + 1], ah[t], bh[1], bh[3]);
                mma_bf16(acc[t][q * 2 + 1], ah[t], bl[1], bl[3]);
            }
        }
    }

    __syncthreads();
    float* zt = (float*)sh;
    {
        int clb = n0 + (lane & 3) * 2;
        int plocal = m0 + (lane >> 2);
#pragma unroll
        for (int t = 0; t < 2; t++) {
            int p0 = plocal + t * 16, p1 = p0 + 8;
#pragma unroll
            for (int q = 0; q < 4; q++) {
                int cl = clb + q * 8;
                zt[cl * 128 + p0]       = acc[t][q][0];
                zt[(cl + 1) * 128 + p0] = acc[t][q][1];
                zt[cl * 128 + p1]       = acc[t][q][2];
                zt[(cl + 1) * 128 + p1] = acc[t][q][3];
            }
        }
    }
    __syncthreads();

#pragma unroll
    for (int k = 0; k < 8; k++) {
        int idx = tid + k * 256;
        int row = idx >> 5, col = idx & 31;
        float4 z4 = ((const float4*)zt)[row * 32 + col];
        float4 sc4 = *(const float4*)(sc_s + col * 4);
        float bb = b2_s[row];
        size_t go = ((size_t)(b * C + cb0 + row)) * NPIX + pix0 + col * 4;
        float4 x4 = *(const float4*)(x + go);
        float4 o;
        o.x = fmaxf(fmaf(z4.x, sc4.x, bb) + x4.x, 0.f);
        o.y = fmaxf(fmaf(z4.y, sc4.y, bb) + x4.y, 0.f);
        o.z = fmaxf(fmaf(z4.z, sc4.z, bb) + x4.z, 0.f);
        o.w = fmaxf(fmaf(z4.w, sc4.w, bb) + x4.w, 0.f);
        *(float4*)(out + go) = o;
    }
}

// ---------------------------------------------------------------------------
extern "C" void kernel_launch(void* const* d_in, const int* in_sizes, int n_in,
                              void* d_out, int out_size)
{
    const float* x       = (const float*)d_in[0];
    const float* conv1_w = (const float*)d_in[1];
    const float* conv1_b = (const float*)d_in[2];
    const float* mk_w    = (const float*)d_in[3];
    const float* mv_w    = (const float*)d_in[4];
    const float* conv2_w = (const float*)d_in[5];
    const float* gamma   = (const float*)d_in[6];
    const float* beta    = (const float*)d_in[7];
    const float* mean    = (const float*)d_in[8];
    const float* var     = (const float*)d_in[9];
    float* out = (float*)d_out;

    cudaFuncSetAttribute(logits_kernel, cudaFuncAttributeMaxDynamicSharedMemorySize, K1_SMEM);
    cudaFuncSetAttribute(output_kernel, cudaFuncAttributeMaxDynamicSharedMemorySize, K3_SMEM);

    prep_kernel<<<130, 256>>>(conv1_w, conv1_b, mk_w, mv_w, conv2_w,
                              gamma, beta, mean, var);

    dim3 g1(NPIX / 128, BATCH);
    logits_kernel<<<g1, 256, K1_SMEM>>>(x);

    rowinv_kernel<<<BATCH, 256>>>();

    dim3 g3((NPIX / 128) * 4, BATCH);
    output_kernel<<<g3, 256, K3_SMEM>>>(x, out);
}

// round 16
// speedup vs baseline: 1.1365x; 1.0314x over previous
#include <cuda_runtime.h>
#include <cuda_bf16.h>
#include <cuda_fp16.h>
#include <cstdint>

#define BATCH 16
#define C 256
#define D 64
#define NPIX 16384

// ---------------- device scratch (no runtime allocation) -------------------
__device__ __nv_bfloat16 g_ebf[(size_t)BATCH * D * NPIX];  // exp(logits), bf16, 32MB
__device__ float g_part[BATCH * D * 128];
__device__ float g_rowinv[BATCH * D];
__device__ __half g_W1h[4 * 64 * 72];                      // [ck][d][72] fp16, padded
__device__ float g_W2f[C * D];                             // fp32 bn-folded W2 [c][d]
__device__ __nv_bfloat16 g_W2b[BATCH * 2 * 256 * 72];      // per-batch W2*ri hi/lo planes
__device__ float g_b1[D];
__device__ float g_bias2[C];

// ---------------- helpers ---------------------------------------------------
__device__ __forceinline__ uint32_t smem_u32(const void* p) {
    uint32_t a;
    asm("{ .reg .u64 t; cvta.to.shared.u64 t, %1; cvt.u32.u64 %0, t; }" : "=r"(a) : "l"(p));
    return a;
}
__device__ __forceinline__ void ldm_x4(uint32_t addr, uint32_t* r) {
    asm volatile("ldmatrix.sync.aligned.m8n8.x4.shared.b16 {%0,%1,%2,%3}, [%4];"
        : "=r"(r[0]), "=r"(r[1]), "=r"(r[2]), "=r"(r[3]) : "r"(addr));
}
__device__ __forceinline__ void ldm_x4t(uint32_t addr, uint32_t* r) {
    asm volatile("ldmatrix.sync.aligned.m8n8.x4.trans.shared.b16 {%0,%1,%2,%3}, [%4];"
        : "=r"(r[0]), "=r"(r[1]), "=r"(r[2]), "=r"(r[3]) : "r"(addr));
}
__device__ __forceinline__ void mma_bf16(float* d, const uint32_t* a, uint32_t b0, uint32_t b1) {
    asm volatile(
        "mma.sync.aligned.m16n8k16.row.col.f32.bf16.bf16.f32 "
        "{%0,%1,%2,%3}, {%4,%5,%6,%7}, {%8,%9}, {%0,%1,%2,%3};"
        : "+f"(d[0]), "+f"(d[1]), "+f"(d[2]), "+f"(d[3])
        : "r"(a[0]), "r"(a[1]), "r"(a[2]), "r"(a[3]), "r"(b0), "r"(b1));
}
__device__ __forceinline__ void mma_f16(float* d, const uint32_t* a, uint32_t b0, uint32_t b1) {
    asm volatile(
        "mma.sync.aligned.m16n8k16.row.col.f32.f16.f16.f32 "
        "{%0,%1,%2,%3}, {%4,%5,%6,%7}, {%8,%9}, {%0,%1,%2,%3};"
        : "+f"(d[0]), "+f"(d[1]), "+f"(d[2]), "+f"(d[3])
        : "r"(a[0]), "r"(a[1]), "r"(a[2]), "r"(a[3]), "r"(b0), "r"(b1));
}
__device__ __forceinline__ void cp16(uint32_t dst, const void* src) {
    asm volatile("cp.async.ca.shared.global [%0], [%1], 16;" :: "r"(dst), "l"(src));
}
__device__ __forceinline__ void cp_commit() { asm volatile("cp.async.commit_group;"); }
__device__ __forceinline__ void cp_wait0() { asm volatile("cp.async.wait_group 0;" ::: "memory"); }

// exp via FMA-pipe polynomial (no MUFU); rel err ~2e-6
__device__ __forceinline__ float fexp(float v) {
    float t = v * 1.44269504f;
    t = fminf(fmaxf(t, -120.f), 120.f);
    float r = rintf(t);
    float f = t - r;
    float q = 0.0013333558f;
    q = fmaf(q, f, 0.0096181291f);
    q = fmaf(q, f, 0.0555041087f);
    q = fmaf(q, f, 0.2402265069f);
    q = fmaf(q, f, 0.6931471806f);
    q = fmaf(q, f, 1.0f);
    return __int_as_float(((int)r + 127) << 23) * q;
}
__device__ __forceinline__ void split_bf16(float v, __nv_bfloat16& hi, __nv_bfloat16& lo) {
    hi = __float2bfloat16(v);
    lo = __float2bfloat16(v - __bfloat162float(hi));
}

// ---------------------------------------------------------------------------
// K0: fold weights + BN.  W1 -> fp16 padded plane; W2 -> fp32 [c][d].
// ---------------------------------------------------------------------------
__global__ __launch_bounds__(256) void prep_kernel(
    const float* __restrict__ conv1_w, const float* __restrict__ conv1_b,
    const float* __restrict__ mk_w,    const float* __restrict__ mv_w,
    const float* __restrict__ conv2_w, const float* __restrict__ bn_gamma,
    const float* __restrict__ bn_beta, const float* __restrict__ bn_mean,
    const float* __restrict__ bn_var)
{
    int gid = blockIdx.x * blockDim.x + threadIdx.x;
    if (gid < D * C) {
        int d = gid >> 8, c = gid & 255;
        float s = 0.f;
        for (int o = 0; o < C; o++)
            s = fmaf(mk_w[d * C + o], conv1_w[o * C + c], s);
        int ck = c >> 6, cl = c & 63;
        g_W1h[ck * 4608 + d * 72 + cl] = __float2half(s);
    } else if (gid < 2 * D * C) {
        int j = gid - D * C;
        int c = j >> 6, d = j & 63;
        float inv = bn_gamma[c] * rsqrtf(bn_var[c] + 1e-5f);
        float s = 0.f;
        for (int cp = 0; cp < C; cp++)
            s = fmaf(conv2_w[c * C + cp], mv_w[cp * D + d], s);
        g_W2f[c * D + d] = s * inv;
    } else if (gid < 2 * D * C + D) {
        int d = gid - 2 * D * C;
        float s = 0.f;
        for (int o = 0; o < C; o++)
            s = fmaf(mk_w[d * C + o], conv1_b[o], s);
        g_b1[d] = s;
    } else if (gid < 2 * D * C + D + C) {
        int c = gid - 2 * D * C - D;
        float inv = bn_gamma[c] * rsqrtf(bn_var[c] + 1e-5f);
        g_bias2[c] = bn_beta[c] - bn_mean[c] * inv;
    }
}

// ---------------------------------------------------------------------------
// K1: e = exp(W1 @ x + b1) -> bf16, + per-block row partial sums.
// fp16 single-plane x and W1 (half the MMAs of the bf16 hi/lo scheme).
// 128 pix x 64 d, K=256 in 4 chunks of 64; cp.async W staging; 4 CTAs/SM.
// ---------------------------------------------------------------------------
#define K1_XH 0                          // 17408
#define K1_W  17408                      // 9216 (single fp16 plane)
#define K1_B1 26624                      // 256
#define K1_SPART 26880                   // 1024
#define K1_SMEM 27904

__global__ __launch_bounds__(256, 4) void logits_kernel(const float* __restrict__ x)
{
    extern __shared__ char sh[];
    uint32_t sb = smem_u32(sh);
    float* b1s   = (float*)(sh + K1_B1);
    float* spart = (float*)(sh + K1_SPART);
    int tid = threadIdx.x, w = tid >> 5, lane = tid & 31;
    int b = blockIdx.y, mblk = blockIdx.x, pix0 = mblk * 128;

    if (tid < 64) b1s[tid] = g_b1[tid];

    int wm = w & 3, wq = w >> 2;
    int m0 = wm * 32, n0 = wq * 32;
    uint32_t a_k = (lane & 7) + ((lane >> 4) << 3);
    uint32_t a_mo = ((lane >> 3) & 1) * 8;
    uint32_t b_row = lane & 15;
    uint32_t b_co = (lane >> 4) << 4;

    float acc[2][4][4];
#pragma unroll
    for (int t = 0; t < 2; t++)
#pragma unroll
        for (int q = 0; q < 4; q++)
#pragma unroll
            for (int i = 0; i < 4; i++) acc[t][q][i] = 0.f;

    for (int ck = 0; ck < 4; ck++) {
        // stage W chunk (single fp16 plane, 576 x 16B) via cp.async
#pragma unroll
        for (int k = 0; k < 3; k++) {
            int idx = tid + k * 256;
            if (idx < 576)
                cp16(sb + K1_W + idx * 16,
                     (const char*)g_W1h + ck * 9216 + idx * 16);
        }
        cp_commit();
        // stage x chunk -> fp16 plane, K-major [c][pix]; float4 loads
        {
            const float* xp = x + ((size_t)b * C + ck * 64 + w * 8) * NPIX + pix0 + lane * 4;
            char* xh = sh + K1_XH + (size_t)(w * 8) * 272 + lane * 8;
#pragma unroll
            for (int jb = 0; jb < 2; jb++) {
                float4 v[4];
#pragma unroll
                for (int u = 0; u < 4; u++)
                    v[u] = *(const float4*)(xp + (size_t)(jb * 4 + u) * NPIX);
#pragma unroll
                for (int u = 0; u < 4; u++) {
                    int j = jb * 4 + u;
                    __half2 lo2 = __floats2half2_rn(v[u].x, v[u].y);
                    __half2 hi2 = __floats2half2_rn(v[u].z, v[u].w);
                    uint2 pp;
                    pp.x = *(uint32_t*)&lo2;
                    pp.y = *(uint32_t*)&hi2;
                    *(uint2*)(xh + j * 272) = pp;
                }
            }
        }
        cp_wait0();
        __syncthreads();

#pragma unroll
        for (int kk = 0; kk < 4; kk++) {
            uint32_t ah[2][4];
#pragma unroll
            for (int t = 0; t < 2; t++) {
                uint32_t off = (kk * 16 + a_k) * 272 + (m0 + t * 16 + a_mo) * 2;
                ldm_x4t(sb + K1_XH + off, ah[t]);
            }
            uint32_t bh[2][4];
#pragma unroll
            for (int q = 0; q < 2; q++) {
                uint32_t off = (n0 + q * 16 + b_row) * 144 + kk * 32 + b_co;
                ldm_x4(sb + K1_W + off, bh[q]);
            }
#pragma unroll
            for (int t = 0; t < 2; t++)
#pragma unroll
                for (int q = 0; q < 2; q++) {
                    mma_f16(acc[t][q * 2], ah[t], bh[q][0], bh[q][2]);
                    mma_f16(acc[t][q * 2 + 1], ah[t], bh[q][1], bh[q][3]);
                }
        }
        __syncthreads();
    }

    // epilogue: exp -> bf16 z-tile [d][128 pix] in smem, + row partials
    __nv_bfloat16* ztb = (__nv_bfloat16*)(sh + K1_XH);
    int dbase = n0 + (lane & 3) * 2;
    int plocal = m0 + (lane >> 2);
#pragma unroll
    for (int q = 0; q < 4; q++) {
        int d0 = dbase + q * 8;
        float bb0 = b1s[d0], bb1 = b1s[d0 + 1];
        float s0 = 0.f, s1 = 0.f;
#pragma unroll
        for (int t = 0; t < 2; t++) {
            int p0 = plocal + t * 16, p1 = p0 + 8;
            float v00 = fexp(acc[t][q][0] + bb0); ztb[d0 * 128 + p0] = __float2bfloat16(v00);
            float v01 = fexp(acc[t][q][1] + bb1); ztb[(d0 + 1) * 128 + p0] = __float2bfloat16(v01);
            float v02 = fexp(acc[t][q][2] + bb0); ztb[d0 * 128 + p1] = __float2bfloat16(v02);
            float v03 = fexp(acc[t][q][3] + bb1); ztb[(d0 + 1) * 128 + p1] = __float2bfloat16(v03);
            s0 += v00 + v02; s1 += v01 + v03;
        }
        s0 += __shfl_xor_sync(0xFFFFFFFF, s0, 4);
        s0 += __shfl_xor_sync(0xFFFFFFFF, s0, 8);
        s0 += __shfl_xor_sync(0xFFFFFFFF, s0, 16);
        s1 += __shfl_xor_sync(0xFFFFFFFF, s1, 4);
        s1 += __shfl_xor_sync(0xFFFFFFFF, s1, 8);
        s1 += __shfl_xor_sync(0xFFFFFFFF, s1, 16);
        if (lane < 4) {
            spart[d0 * 4 + wm] = s0;
            spart[(d0 + 1) * 4 + wm] = s1;
        }
    }
    __syncthreads();
    if (tid < 64) {
        float s = spart[tid * 4] + spart[tid * 4 + 1] + spart[tid * 4 + 2] + spart[tid * 4 + 3];
        g_part[(b * D + tid) * 128 + mblk] = s;
    }
    // coalesced bf16 store: 1024 x 16B items
#pragma unroll
    for (int k = 0; k < 4; k++) {
        int idx = tid + k * 256;
        int row = idx >> 4, ch = idx & 15;
        uint4 v = *(uint4*)((char*)ztb + row * 256 + ch * 16);
        *(uint4*)((char*)g_ebf + ((size_t)(b * D + row) * NPIX + pix0) * 2 + ch * 16) = v;
    }
}

// ---------------------------------------------------------------------------
// K2: rowinv + per-batch W2' = W2 * ri[d] -> padded bf16 hi/lo planes.
// ---------------------------------------------------------------------------
__global__ __launch_bounds__(256) void rowinv_kernel()
{
    __shared__ float ri_s[64];
    __shared__ float red[256];
    int b = blockIdx.x, tid = threadIdx.x;
    int r = tid >> 2, qq = tid & 3;
    float s = 0.f;
#pragma unroll
    for (int i = 0; i < 32; i++)
        s += g_part[(b * D + r) * 128 + qq * 32 + i];
    red[tid] = s;
    __syncthreads();
    if (qq == 0) {
        float t = red[tid] + red[tid + 1] + red[tid + 2] + red[tid + 3];
        float ri = 1.f / t;
        ri_s[r] = ri;
        g_rowinv[b * D + r] = ri;
    }
    __syncthreads();
#pragma unroll
    for (int k = 0; k < 64; k++) {
        int idx = tid + k * 256;
        int c = idx >> 6, d = idx & 63;
        float wv = g_W2f[idx] * ri_s[d];
        __nv_bfloat16 hi, lo; split_bf16(wv, hi, lo);
        g_W2b[(size_t)b * 36864 + c * 72 + d] = hi;
        g_W2b[(size_t)b * 36864 + 18432 + c * 72 + d] = lo;
    }
}

// ---------------------------------------------------------------------------
// K3: out = relu(W2' @ e * scale + bias2 + x); scale = 1/(1e-9 + colsum(ri*e)).
// (unchanged from R15: 128 pix x 64 c, bf16 A, 4 CTAs/SM)
// ---------------------------------------------------------------------------
#define K3_A  0
#define K3_W  17408
#define K3_RI (K3_W + 18432)
#define K3_B2 (K3_RI + 256)
#define K3_CS (K3_B2 + 256)
#define K3_SC (K3_CS + 2048)
#define K3_SMEM (K3_SC + 512)

__global__ __launch_bounds__(256, 4) void output_kernel(const float* __restrict__ x,
                                                        float* __restrict__ out)
{
    extern __shared__ char sh[];
    uint32_t sb = smem_u32(sh);
    float* ri_s = (float*)(sh + K3_RI);
    float* b2_s = (float*)(sh + K3_B2);
    float* cs   = (float*)(sh + K3_CS);
    float* sc_s = (float*)(sh + K3_SC);
    int tid = threadIdx.x, w = tid >> 5, lane = tid & 31;
    int b = blockIdx.y;
    int cblk = blockIdx.x & 3, pixblk = blockIdx.x >> 2;
    int pix0 = pixblk * 128, cb0 = cblk * 64;

#pragma unroll
    for (int k = 0; k < 4; k++) {
        int idx = tid + k * 256;
        int d = idx >> 4, ch = idx & 15;
        cp16(sb + K3_A + d * 272 + ch * 16,
             (const char*)g_ebf + ((size_t)(b * D + d) * NPIX + pix0) * 2 + ch * 16);
    }
#pragma unroll
    for (int k = 0; k < 5; k++) {
        int idx = tid + k * 256;
        if (idx < 1152) {
            int plane = idx / 576, r = idx % 576;
            cp16(sb + K3_W + plane * 9216 + r * 16,
                 (const char*)g_W2b + (size_t)b * 73728 + plane * 36864 + cb0 * 144 + r * 16);
        }
    }
    cp_commit();
    if (tid < 64) {
        ri_s[tid] = g_rowinv[b * D + tid];
        b2_s[tid] = g_bias2[cb0 + tid];
    }
    cp_wait0();
    __syncthreads();

    // colsum over d of ri*e -> per-pixel scale (bf16x2 vectorized)
    {
        int pair = tid & 63;
        int dg = tid >> 6;
        float s0 = 0.f, s1 = 0.f;
#pragma unroll
        for (int j = 0; j < 16; j++) {
            int d = dg * 16 + j;
            __nv_bfloat162 e2 = *(const __nv_bfloat162*)(sh + K3_A + d * 272 + pair * 4);
            float ri = ri_s[d];
            s0 = fmaf(__bfloat162float(e2.x), ri, s0);
            s1 = fmaf(__bfloat162float(e2.y), ri, s1);
        }
        cs[dg * 128 + pair * 2]     = s0;
        cs[dg * 128 + pair * 2 + 1] = s1;
    }
    __syncthreads();
    if (tid < 128)
        sc_s[tid] = 1.f / (1e-9f + cs[tid] + cs[128 + tid] + cs[256 + tid] + cs[384 + tid]);
    __syncthreads();

    int wm = w & 3, wq = w >> 2;
    int m0 = wm * 32, n0 = wq * 32;
    uint32_t a_k = (lane & 7) + ((lane >> 4) << 3);
    uint32_t a_mo = ((lane >> 3) & 1) * 8;
    uint32_t b_row = lane & 15;
    uint32_t b_co = (lane >> 4) << 4;

    float acc[2][4][4];
#pragma unroll
    for (int t = 0; t < 2; t++)
#pragma unroll
        for (int q = 0; q < 4; q++)
#pragma unroll
            for (int i = 0; i < 4; i++) acc[t][q][i] = 0.f;

#pragma unroll
    for (int kk = 0; kk < 4; kk++) {
        uint32_t ah[2][4];
#pragma unroll
        for (int t = 0; t < 2; t++) {
            uint32_t off = (kk * 16 + a_k) * 272 + (m0 + t * 16 + a_mo) * 2;
            ldm_x4t(sb + K3_A + off, ah[t]);
        }
#pragma unroll
        for (int q = 0; q < 2; q++) {
            uint32_t off = (n0 + q * 16 + b_row) * 144 + kk * 32 + b_co;
            uint32_t bh[4], bl[4];
            ldm_x4(sb + K3_W + off, bh);
            ldm_x4(sb + K3_W + 9216 + off, bl);
#pragma unroll
            for (int t = 0; t < 2; t++) {
                mma_bf16(acc[t][q * 2], ah[t], bh[0], bh[2]);
                mma_bf16(acc[t][q * 2], ah[t], bl[0], bl[2]);
                mma_bf16(acc[t][q * 2 + 1], ah[t], bh[1], bh[3]);
                mma_bf16(acc[t][q * 2 + 1], ah[t], bl[1], bl[3]);
            }
        }
    }

    __syncthreads();
    float* zt = (float*)sh;
    {
        int clb = n0 + (lane & 3) * 2;
        int plocal = m0 + (lane >> 2);
#pragma unroll
        for (int t = 0; t < 2; t++) {
            int p0 = plocal + t * 16, p1 = p0 + 8;
#pragma unroll
            for (int q = 0; q < 4; q++) {
                int cl = clb + q * 8;
                zt[cl * 128 + p0]       = acc[t][q][0];
                zt[(cl + 1) * 128 + p0] = acc[t][q][1];
                zt[cl * 128 + p1]       = acc[t][q][2];
                zt[(cl + 1) * 128 + p1] = acc[t][q][3];
            }
        }
    }
    __syncthreads();

#pragma unroll
    for (int k = 0; k < 8; k++) {
        int idx = tid + k * 256;
        int row = idx >> 5, col = idx & 31;
        float4 z4 = ((const float4*)zt)[row * 32 + col];
        float4 sc4 = *(const float4*)(sc_s + col * 4);
        float bb = b2_s[row];
        size_t go = ((size_t)(b * C + cb0 + row)) * NPIX + pix0 + col * 4;
        float4 x4 = *(const float4*)(x + go);
        float4 o;
        o.x = fmaxf(fmaf(z4.x, sc4.x, bb) + x4.x, 0.f);
        o.y = fmaxf(fmaf(z4.y, sc4.y, bb) + x4.y, 0.f);
        o.z = fmaxf(fmaf(z4.z, sc4.z, bb) + x4.z, 0.f);
        o.w = fmaxf(fmaf(z4.w, sc4.w, bb) + x4.w, 0.f);
        *(float4*)(out + go) = o;
    }
}

// ---------------------------------------------------------------------------
extern "C" void kernel_launch(void* const* d_in, const int* in_sizes, int n_in,
                              void* d_out, int out_size)
{
    const float* x       = (const float*)d_in[0];
    const float* conv1_w = (const float*)d_in[1];
    const float* conv1_b = (const float*)d_in[2];
    const float* mk_w    = (const float*)d_in[3];
    const float* mv_w    = (const float*)d_in[4];
    const float* conv2_w = (const float*)d_in[5];
    const float* gamma   = (const float*)d_in[6];
    const float* beta    = (const float*)d_in[7];
    const float* mean    = (const float*)d_in[8];
    const float* var     = (const float*)d_in[9];
    float* out = (float*)d_out;

    cudaFuncSetAttribute(logits_kernel, cudaFuncAttributeMaxDynamicSharedMemorySize, K1_SMEM);
    cudaFuncSetAttribute(output_kernel, cudaFuncAttributeMaxDynamicSharedMemorySize, K3_SMEM);

    prep_kernel<<<130, 256>>>(conv1_w, conv1_b, mk_w, mv_w, conv2_w,
                              gamma, beta, mean, var);

    dim3 g1(NPIX / 128, BATCH);
    logits_kernel<<<g1, 256, K1_SMEM>>>(x);

    rowinv_kernel<<<BATCH, 256>>>();

    dim3 g3((NPIX / 128) * 4, BATCH);
    output_kernel<<<g3, 256, K3_SMEM>>>(x, out);
}